// round 1
// baseline (speedup 1.0000x reference)
#include <cuda_runtime.h>
#include <cuda_fp16.h>

// WaveletWindowAttention fused single-kernel implementation.
// One CTA per 8x8 window (in half-res domain): 512 CTAs, 512 threads.
// Phases: A) 2x2 wavelet fwd into smem  B) 8 sequential attention heads
//         C) 256x256 projection        D) inverse wavelet -> d_out
//
// Sizes: B=2, C=256, RES=256, H2=128, FWS=8, N=64 px/window, HD=32, HEADS=8.

#define NTH 512

__device__ __forceinline__ float2 ffma2(float2 a, float2 b, float2 c) {
    unsigned long long ua = *reinterpret_cast<unsigned long long*>(&a);
    unsigned long long ub = *reinterpret_cast<unsigned long long*>(&b);
    unsigned long long uc = *reinterpret_cast<unsigned long long*>(&c);
    unsigned long long ud;
    asm("fma.rn.f32x2 %0, %1, %2, %3;" : "=l"(ud) : "l"(ua), "l"(ub), "l"(uc));
    return *reinterpret_cast<float2*>(&ud);
}

// ---- shared memory layout (bytes) ----
// S_ll   f32 [256][64]        @ 0       (65536)  ll -> head outputs -> ll_out
// S_lh   f16 [256][64]        @ 65536   (32768)
// S_hl   f16 [256][64]        @ 98304   (32768)
// S_hh   f16 [256][64]        @ 131072  (32768)
// Z scratch                   @ 163840:
//   S_q    f32 [64][33]       Z+0       (8448)
//   S_at   f32 [64][66]       Z+8448    (16896)
//   S_v    f32 [32][64]       Z+25344   (8192)
//   S_dw   f32 [800]          Z+33536   (3200)
//   S_db   f32 [32]           Z+36736   (128)
//   S_bi   u8  [4096]         Z+36864   (4096)
//   S_ab   f32 [512]          Z+40960   (2048)
//   aliases over Z: S_wt f32[4096] (phase A), S_ws f32[32*257] (phase C),
//                   S_iw f32[4096] (phase D)
#define SMEM_BYTES 206848

__global__ void __launch_bounds__(NTH, 1)
wwa_kernel(const float* __restrict__ x,   const float* __restrict__ wtf,
           const float* __restrict__ iwtf,const float* __restrict__ dww,
           const float* __restrict__ dwb, const float* __restrict__ pjw,
           const float* __restrict__ pjb, const float* __restrict__ atb,
           const int*   __restrict__ bix, float* __restrict__ out)
{
    extern __shared__ unsigned char sm[];
    float*  S_ll = (float*)sm;
    __half* S_lh = (__half*)(sm + 65536);
    __half* S_hl = (__half*)(sm + 98304);
    __half* S_hh = (__half*)(sm + 131072);
    unsigned char* Z = sm + 163840;
    float* S_q  = (float*)Z;
    float* S_at = (float*)(Z + 8448);
    float* S_v  = (float*)(Z + 25344);
    float* S_dw = (float*)(Z + 33536);
    float* S_db = (float*)(Z + 36736);
    unsigned char* S_bi = Z + 36864;
    float* S_ab = (float*)(Z + 40960);
    float* S_wt = (float*)Z;   // phase A alias
    float* S_ws = (float*)Z;   // phase C alias (stride 257)
    float* S_iw = (float*)Z;   // phase D alias

    const int tid  = threadIdx.x;
    const int widx = blockIdx.x;
    const int wb = widx >> 8;          // batch
    const int wy = (widx >> 4) & 15;   // window row
    const int wx = widx & 15;          // window col

    // ---- load small tables ----
    for (int i = tid; i < 4096; i += NTH) S_wt[i] = wtf[i];
    for (int i = tid; i < 4096; i += NTH) S_bi[i] = (unsigned char)bix[i];
    for (int i = tid; i < 512;  i += NTH) S_ab[i] = atb[i];
    __syncthreads();

    // ================= Phase A: forward wavelet =================
    // subband[s][c][i][j] = sum_{r,c2} x[c][2i+r][2j+c2] * wtf[(4c+s)*4 + r*2 + c2]
    {
        const float* xb = x + (size_t)wb * (256u * 256u * 256u);
        #pragma unroll 4
        for (int rep = 0; rep < 16; rep++) {
            int u = tid + rep * NTH;        // 0..8191 = (c, i, k)
            int c = u >> 5;
            int i = (u >> 2) & 7;
            int k = u & 3;
            int gy = (wy << 4) + (i << 1);
            int gx = (wx << 4) + (k << 2);
            const float* p = xb + (((c << 8) + gy) << 8) + gx;
            float4 a = *(const float4*)p;
            float4 b = *(const float4*)(p + 256);
            const float* w = S_wt + (c << 4);
            int o0 = (c << 6) + (i << 3) + (k << 1);
            float v0, v1;
            v0 = a.x*w[0] + a.y*w[1] + b.x*w[2] + b.y*w[3];
            v1 = a.z*w[0] + a.w*w[1] + b.z*w[2] + b.w*w[3];
            S_ll[o0] = v0; S_ll[o0 + 1] = v1;
            v0 = a.x*w[4] + a.y*w[5] + b.x*w[6] + b.y*w[7];
            v1 = a.z*w[4] + a.w*w[5] + b.z*w[6] + b.w*w[7];
            *(__half2*)(S_lh + o0) = __floats2half2_rn(v0, v1);
            v0 = a.x*w[8] + a.y*w[9] + b.x*w[10] + b.y*w[11];
            v1 = a.z*w[8] + a.w*w[9] + b.z*w[10] + b.w*w[11];
            *(__half2*)(S_hl + o0) = __floats2half2_rn(v0, v1);
            v0 = a.x*w[12] + a.y*w[13] + b.x*w[14] + b.y*w[15];
            v1 = a.z*w[12] + a.w*w[13] + b.z*w[14] + b.w*w[15];
            *(__half2*)(S_hh + o0) = __floats2half2_rn(v0, v1);
        }
    }
    __syncthreads();

    // ================= Phase B: 8 sequential heads =================
    for (int hd = 0; hd < 8; hd++) {
        const int ch0 = hd << 5;
        // per-head depthwise weights
        for (int i = tid; i < 800; i += NTH) S_dw[i] = dww[hd * 800 + i];
        if (tid < 32) S_db[tid] = dwb[(hd << 5) + tid];
        // v = chain: prev head's output (stored at sl-32) + original ll[sl]
        #pragma unroll
        for (int rep = 0; rep < 4; rep++) {
            int e = tid + rep * NTH;   // 0..2047
            int d = e >> 6, m = e & 63;
            float v = S_ll[((ch0 + d) << 6) + m];
            if (hd > 0) v += S_ll[((ch0 - 32 + d) << 6) + m];
            S_v[(d << 6) + m] = v;
        }
        __syncthreads();
        // q = depthwise 5x5 conv of lh window (zero pad) + bias -> S_q[n][d]
        #pragma unroll
        for (int rep = 0; rep < 4; rep++) {
            int e = tid + rep * NTH;
            int n = e >> 5, d = e & 31;
            int py = n >> 3, px = n & 7;
            float acc = S_db[d];
            const float* wd = S_dw + d * 25;
            const __half* lhr = S_lh + ((ch0 + d) << 6);
            #pragma unroll
            for (int uu = 0; uu < 5; uu++) {
                int yy = py + uu - 2;
                if ((unsigned)yy < 8u) {
                    #pragma unroll
                    for (int vv = 0; vv < 5; vv++) {
                        int xx = px + vv - 2;
                        if ((unsigned)xx < 8u)
                            acc += __half2float(lhr[(yy << 3) + xx]) * wd[uu * 5 + vv];
                    }
                }
            }
            S_q[n * 33 + d] = acc;
        }
        __syncthreads();
        // attn[n][m] = softmax_m( SCALE * q[n]·k[:,m] + bias )
        {
            const int n  = tid >> 3;
            const int m0 = (tid & 7) << 3;
            float2 v2[4];
            v2[0] = v2[1] = v2[2] = v2[3] = make_float2(0.f, 0.f);
            const float* qr = S_q + n * 33;
            #pragma unroll 4
            for (int d = 0; d < 32; d++) {
                float qv = qr[d];
                float2 q2 = make_float2(qv, qv);
                const __half2* kr = (const __half2*)(S_hl + ((ch0 + d) << 6) + m0);
                v2[0] = ffma2(q2, __half22float2(kr[0]), v2[0]);
                v2[1] = ffma2(q2, __half22float2(kr[1]), v2[1]);
                v2[2] = ffma2(q2, __half22float2(kr[2]), v2[2]);
                v2[3] = ffma2(q2, __half22float2(kr[3]), v2[3]);
            }
            float fv[8];
            const unsigned char* bp = S_bi + (n << 6) + m0;
            const float* ab = S_ab + (hd << 6);
            #pragma unroll
            for (int p = 0; p < 4; p++) {
                fv[2*p]   = v2[p].x * 0.17677669529663687f + ab[bp[2*p]];
                fv[2*p+1] = v2[p].y * 0.17677669529663687f + ab[bp[2*p+1]];
            }
            float mx = fv[0];
            #pragma unroll
            for (int j = 1; j < 8; j++) mx = fmaxf(mx, fv[j]);
            mx = fmaxf(mx, __shfl_xor_sync(0xffffffffu, mx, 1));
            mx = fmaxf(mx, __shfl_xor_sync(0xffffffffu, mx, 2));
            mx = fmaxf(mx, __shfl_xor_sync(0xffffffffu, mx, 4));
            float sum = 0.f;
            #pragma unroll
            for (int j = 0; j < 8; j++) { fv[j] = __expf(fv[j] - mx); sum += fv[j]; }
            sum += __shfl_xor_sync(0xffffffffu, sum, 1);
            sum += __shfl_xor_sync(0xffffffffu, sum, 2);
            sum += __shfl_xor_sync(0xffffffffu, sum, 4);
            float inv = 1.f / sum;
            #pragma unroll
            for (int j = 0; j < 8; j++) S_at[n * 66 + m0 + j] = fv[j] * inv;
        }
        __syncthreads();
        // out[d][n] = sum_m v[d][m] * attn[n][m]  -> overwrite S_ll[sl]
        #pragma unroll
        for (int rep = 0; rep < 4; rep++) {
            int e = tid + rep * NTH;
            int d = e >> 6, nn = e & 63;
            const float2* vv = (const float2*)(S_v + (d << 6));
            const float2* pp = (const float2*)(S_at + nn * 66);
            float2 acc = make_float2(0.f, 0.f);
            #pragma unroll 8
            for (int m = 0; m < 32; m++) acc = ffma2(vv[m], pp[m], acc);
            S_ll[((ch0 + d) << 6) + nn] = acc.x + acc.y;
        }
        __syncthreads();
    }

    // ================= Phase C: relu + 256x256 projection =================
    for (int i = tid; i < 16384; i += NTH) S_ll[i] = fmaxf(S_ll[i], 0.f);
    __syncthreads();
    {
        const int orow = tid >> 3;        // 0..63
        const int n0   = (tid & 7) << 3;  // 0,8,...,56
        float2 acc[4][4];
        #pragma unroll
        for (int a_ = 0; a_ < 4; a_++)
            #pragma unroll
            for (int b_ = 0; b_ < 4; b_++) acc[a_][b_] = make_float2(0.f, 0.f);

        for (int cb = 0; cb < 8; cb++) {
            // stage W[:, cb*32 .. +32] transposed into smem, stride 257
            #pragma unroll
            for (int r = 0; r < 4; r++) {
                int li = tid + r * NTH;     // 0..2047
                int o  = li >> 3;
                int c4 = li & 7;
                float4 w4 = *(const float4*)(pjw + (o << 8) + (cb << 5) + (c4 << 2));
                int cc = c4 << 2;
                S_ws[cc * 257 + o]       = w4.x;
                S_ws[(cc + 1) * 257 + o] = w4.y;
                S_ws[(cc + 2) * 257 + o] = w4.z;
                S_ws[(cc + 3) * 257 + o] = w4.w;
            }
            __syncthreads();
            #pragma unroll 2
            for (int cc = 0; cc < 32; cc++) {
                int c = (cb << 5) + cc;
                const float4* ar = (const float4*)(S_ll + (c << 6) + n0);
                float4 A0 = ar[0], A1 = ar[1];
                float2 a0 = make_float2(A0.x, A0.y);
                float2 a1 = make_float2(A0.z, A0.w);
                float2 a2 = make_float2(A1.x, A1.y);
                float2 a3 = make_float2(A1.z, A1.w);
                const float* wr = S_ws + cc * 257 + orow;
                #pragma unroll
                for (int oo = 0; oo < 4; oo++) {
                    float wv = wr[oo << 6];
                    float2 w2 = make_float2(wv, wv);
                    acc[oo][0] = ffma2(a0, w2, acc[oo][0]);
                    acc[oo][1] = ffma2(a1, w2, acc[oo][1]);
                    acc[oo][2] = ffma2(a2, w2, acc[oo][2]);
                    acc[oo][3] = ffma2(a3, w2, acc[oo][3]);
                }
            }
            __syncthreads();
        }
        // bias + write ll_out back into S_ll
        #pragma unroll
        for (int oo = 0; oo < 4; oo++) {
            int o = orow + (oo << 6);
            float pb = pjb[o];
            float* dst = S_ll + (o << 6) + n0;
            dst[0] = acc[oo][0].x + pb; dst[1] = acc[oo][0].y + pb;
            dst[2] = acc[oo][1].x + pb; dst[3] = acc[oo][1].y + pb;
            dst[4] = acc[oo][2].x + pb; dst[5] = acc[oo][2].y + pb;
            dst[6] = acc[oo][3].x + pb; dst[7] = acc[oo][3].y + pb;
        }
    }
    __syncthreads();

    // ================= Phase D: inverse wavelet -> out =================
    // out[c][2i+r][2j+c2] = sum_s sub_s[c][i][j] * iwtf[(4c+s)*4 + r*2 + c2]
    for (int i = tid; i < 4096; i += NTH) S_iw[i] = iwtf[i];
    __syncthreads();
    {
        float* ob = out + (size_t)wb * (256u * 256u * 256u);
        #pragma unroll 4
        for (int rep = 0; rep < 16; rep++) {
            int u = tid + rep * NTH;
            int c = u >> 5;
            int i = (u >> 2) & 7;
            int k = u & 3;
            int o0 = (c << 6) + (i << 3) + (k << 1);
            const float* w = S_iw + (c << 4);
            float ll0 = S_ll[o0], ll1 = S_ll[o0 + 1];
            float2 lh = __half22float2(*(const __half2*)(S_lh + o0));
            float2 hl = __half22float2(*(const __half2*)(S_hl + o0));
            float2 hh = __half22float2(*(const __half2*)(S_hh + o0));
            float4 r0, r1;
            r0.x = ll0*w[0] + lh.x*w[4] + hl.x*w[8]  + hh.x*w[12];
            r0.y = ll0*w[1] + lh.x*w[5] + hl.x*w[9]  + hh.x*w[13];
            r0.z = ll1*w[0] + lh.y*w[4] + hl.y*w[8]  + hh.y*w[12];
            r0.w = ll1*w[1] + lh.y*w[5] + hl.y*w[9]  + hh.y*w[13];
            r1.x = ll0*w[2] + lh.x*w[6] + hl.x*w[10] + hh.x*w[14];
            r1.y = ll0*w[3] + lh.x*w[7] + hl.x*w[11] + hh.x*w[15];
            r1.z = ll1*w[2] + lh.y*w[6] + hl.y*w[10] + hh.y*w[14];
            r1.w = ll1*w[3] + lh.y*w[7] + hl.y*w[11] + hh.y*w[15];
            int gy = (wy << 4) + (i << 1);
            int gx = (wx << 4) + (k << 2);
            float* q_ = ob + (((c << 8) + gy) << 8) + gx;
            *(float4*)q_ = r0;
            *(float4*)(q_ + 256) = r1;
        }
    }
}

extern "C" void kernel_launch(void* const* d_in, const int* in_sizes, int n_in,
                              void* d_out, int out_size) {
    const float* x    = (const float*)d_in[0];
    const float* wtf  = (const float*)d_in[1];
    const float* iwtf = (const float*)d_in[2];
    const float* dww  = (const float*)d_in[3];
    const float* dwb  = (const float*)d_in[4];
    const float* pjw  = (const float*)d_in[5];
    const float* pjb  = (const float*)d_in[6];
    const float* atb  = (const float*)d_in[7];
    const int*   bix  = (const int*)d_in[8];
    float* o = (float*)d_out;
    (void)in_sizes; (void)n_in; (void)out_size;
    cudaFuncSetAttribute(wwa_kernel, cudaFuncAttributeMaxDynamicSharedMemorySize, SMEM_BYTES);
    wwa_kernel<<<512, NTH, SMEM_BYTES>>>(x, wtf, iwtf, dww, dwb, pjw, pjb, atb, bix, o);
}

// round 2
// speedup vs baseline: 2.3515x; 2.3515x over previous
#include <cuda_runtime.h>
#include <cuda_fp16.h>

// WaveletWindowAttention fused single-kernel implementation (R2).
// One CTA per 8x8 window (half-res domain): 512 CTAs, 512 threads.
// R2 changes vs R1: conflict-free q-conv lane mapping, LDS.128 vectorization
// of QK^T / PV / proj-weight reads, stride-68 attn matrix, pre-reordered
// projection weights in __device__ scratch.

#define NTH 512

__device__ float g_Wp[65536];   // reordered proj weights: [cb][cc][ (o&63)*4 + (o>>6) ]

__device__ __forceinline__ float2 ffma2(float2 a, float2 b, float2 c) {
    unsigned long long ua = *reinterpret_cast<unsigned long long*>(&a);
    unsigned long long ub = *reinterpret_cast<unsigned long long*>(&b);
    unsigned long long uc = *reinterpret_cast<unsigned long long*>(&c);
    unsigned long long ud;
    asm("fma.rn.f32x2 %0, %1, %2, %3;" : "=l"(ud) : "l"(ua), "l"(ub), "l"(uc));
    return *reinterpret_cast<float2*>(&ud);
}

__global__ void prep_kernel(const float* __restrict__ pjw) {
    int i = blockIdx.x * 256 + threadIdx.x;      // 65536 total
    int o = i >> 8, c = i & 255;
    g_Wp[((c >> 5) << 13) + ((c & 31) << 8) + ((o & 63) << 2) + (o >> 6)] =
        pjw[(o << 8) + c];
}

// ---- shared memory layout (bytes) ----
// S_ll f32 [256][64] @0 (65536)   S_lh/S_hl/S_hh f16 [256][64] @65536/98304/131072
// Z @163840:
//   S_q  f32[64][33]  Z+0      (8448)
//   S_at f32[64][68]  Z+8448   (17408)
//   S_v  f32[32][64]  Z+25856  (8192)
//   S_dw f32[800]     Z+34048  (3200)
//   S_db f32[32]      Z+37248  (128)
//   S_bi u8[4096]     Z+37376  (4096)
//   S_ab f32[512]     Z+41472  (2048)    end 43520
//   aliases: S_wt f32[4096] (phase A), S_ws f32[8192] (phase C), S_iw (phase D)
#define SMEM_BYTES 207360

__global__ void __launch_bounds__(NTH, 1)
wwa_kernel(const float* __restrict__ x,   const float* __restrict__ wtf,
           const float* __restrict__ iwtf,const float* __restrict__ dww,
           const float* __restrict__ dwb, const float* __restrict__ pjb,
           const float* __restrict__ atb, const int* __restrict__ bix,
           float* __restrict__ out)
{
    extern __shared__ unsigned char sm[];
    float*  S_ll = (float*)sm;
    __half* S_lh = (__half*)(sm + 65536);
    __half* S_hl = (__half*)(sm + 98304);
    __half* S_hh = (__half*)(sm + 131072);
    unsigned char* Z = sm + 163840;
    float* S_q  = (float*)Z;
    float* S_at = (float*)(Z + 8448);
    float* S_v  = (float*)(Z + 25856);
    float* S_dw = (float*)(Z + 34048);
    float* S_db = (float*)(Z + 37248);
    unsigned char* S_bi = Z + 37376;
    float* S_ab = (float*)(Z + 41472);
    float* S_wt = (float*)Z;   // phase A alias
    float* S_ws = (float*)Z;   // phase C alias (32x256 contiguous)
    float* S_iw = (float*)Z;   // phase D alias

    const int tid  = threadIdx.x;
    const int widx = blockIdx.x;
    const int wb = widx >> 8;
    const int wy = (widx >> 4) & 15;
    const int wx = widx & 15;

    for (int i = tid; i < 4096; i += NTH) S_wt[i] = wtf[i];
    for (int i = tid; i < 4096; i += NTH) S_bi[i] = (unsigned char)bix[i];
    for (int i = tid; i < 512;  i += NTH) S_ab[i] = atb[i];
    __syncthreads();

    // ================= Phase A: forward wavelet =================
    {
        const float* xb = x + (size_t)wb * (256u * 256u * 256u);
        #pragma unroll 4
        for (int rep = 0; rep < 16; rep++) {
            int u = tid + rep * NTH;        // (c, i, k)
            int c = u >> 5;
            int i = (u >> 2) & 7;
            int k = u & 3;
            int gy = (wy << 4) + (i << 1);
            int gx = (wx << 4) + (k << 2);
            const float* p = xb + (((c << 8) + gy) << 8) + gx;
            float4 a = *(const float4*)p;
            float4 b = *(const float4*)(p + 256);
            const float* w = S_wt + (c << 4);
            int o0 = (c << 6) + (i << 3) + (k << 1);
            float v0, v1;
            v0 = a.x*w[0] + a.y*w[1] + b.x*w[2] + b.y*w[3];
            v1 = a.z*w[0] + a.w*w[1] + b.z*w[2] + b.y*0.f + b.w*w[3];
            v1 = a.z*w[0] + a.w*w[1] + b.z*w[2] + b.w*w[3];
            S_ll[o0] = v0; S_ll[o0 + 1] = v1;
            v0 = a.x*w[4] + a.y*w[5] + b.x*w[6] + b.y*w[7];
            v1 = a.z*w[4] + a.w*w[5] + b.z*w[6] + b.w*w[7];
            *(__half2*)(S_lh + o0) = __floats2half2_rn(v0, v1);
            v0 = a.x*w[8] + a.y*w[9] + b.x*w[10] + b.y*w[11];
            v1 = a.z*w[8] + a.w*w[9] + b.z*w[10] + b.w*w[11];
            *(__half2*)(S_hl + o0) = __floats2half2_rn(v0, v1);
            v0 = a.x*w[12] + a.y*w[13] + b.x*w[14] + b.y*w[15];
            v1 = a.z*w[12] + a.w*w[13] + b.z*w[14] + b.w*w[15];
            *(__half2*)(S_hh + o0) = __floats2half2_rn(v0, v1);
        }
    }
    __syncthreads();

    // ================= Phase B: 8 sequential heads =================
    for (int hd = 0; hd < 8; hd++) {
        const int ch0 = hd << 5;
        for (int i = tid; i < 800; i += NTH) S_dw[i] = dww[hd * 800 + i];
        if (tid < 32) S_db[tid] = dwb[(hd << 5) + tid];
        // v = prev head output (ch0-32 slot) + original ll[ch0 slot]
        #pragma unroll
        for (int rep = 0; rep < 4; rep++) {
            int e = tid + rep * NTH;   // d = e>>6 (warp-uniform), m = e&63
            int d = e >> 6, m = e & 63;
            float v = S_ll[((ch0 + d) << 6) + m];
            if (hd > 0) v += S_ll[((ch0 - 32 + d) << 6) + m];
            S_v[(d << 6) + m] = v;
        }
        __syncthreads();
        // q = depthwise 5x5 conv (zero pad) + bias -> S_q[n][d]
        // lane dim = spatial n (conflict-free), d warp-uniform
        #pragma unroll
        for (int rep = 0; rep < 4; rep++) {
            int e = tid + rep * NTH;
            int d = e >> 6, n = e & 63;
            int py = n >> 3, px = n & 7;
            float acc = S_db[d];
            const float* wd = S_dw + d * 25;
            const __half* lhr = S_lh + ((ch0 + d) << 6);
            #pragma unroll
            for (int uu = 0; uu < 5; uu++) {
                int yy = py + uu - 2;
                if ((unsigned)yy < 8u) {
                    #pragma unroll
                    for (int vv = 0; vv < 5; vv++) {
                        int xx = px + vv - 2;
                        if ((unsigned)xx < 8u)
                            acc += __half2float(lhr[(yy << 3) + xx]) * wd[uu * 5 + vv];
                    }
                }
            }
            S_q[n * 33 + d] = acc;
        }
        __syncthreads();
        // attn[n][m] = softmax_m( SCALE * q[n].k[:,m] + bias[n][m] )
        {
            const int n  = tid >> 3;
            const int m0 = (tid & 7) << 3;
            float2 v2[4];
            v2[0] = v2[1] = v2[2] = v2[3] = make_float2(0.f, 0.f);
            const float* qr = S_q + n * 33;
            #pragma unroll 4
            for (int d = 0; d < 32; d++) {
                float qv = qr[d];
                float2 q2 = make_float2(qv, qv);
                uint4 kv = *(const uint4*)(S_hl + ((ch0 + d) << 6) + m0);  // 8 halves
                v2[0] = ffma2(q2, __half22float2(*(__half2*)&kv.x), v2[0]);
                v2[1] = ffma2(q2, __half22float2(*(__half2*)&kv.y), v2[1]);
                v2[2] = ffma2(q2, __half22float2(*(__half2*)&kv.z), v2[2]);
                v2[3] = ffma2(q2, __half22float2(*(__half2*)&kv.w), v2[3]);
            }
            float fv[8];
            const unsigned char* bp = S_bi + (n << 6) + m0;
            const float* ab = S_ab + (hd << 6);
            #pragma unroll
            for (int p = 0; p < 4; p++) {
                fv[2*p]   = v2[p].x * 0.17677669529663687f + ab[bp[2*p]];
                fv[2*p+1] = v2[p].y * 0.17677669529663687f + ab[bp[2*p+1]];
            }
            float mx = fv[0];
            #pragma unroll
            for (int j = 1; j < 8; j++) mx = fmaxf(mx, fv[j]);
            mx = fmaxf(mx, __shfl_xor_sync(0xffffffffu, mx, 1));
            mx = fmaxf(mx, __shfl_xor_sync(0xffffffffu, mx, 2));
            mx = fmaxf(mx, __shfl_xor_sync(0xffffffffu, mx, 4));
            float sum = 0.f;
            #pragma unroll
            for (int j = 0; j < 8; j++) { fv[j] = __expf(fv[j] - mx); sum += fv[j]; }
            sum += __shfl_xor_sync(0xffffffffu, sum, 1);
            sum += __shfl_xor_sync(0xffffffffu, sum, 2);
            sum += __shfl_xor_sync(0xffffffffu, sum, 4);
            float inv = 1.f / sum;
            float4 w0 = make_float4(fv[0]*inv, fv[1]*inv, fv[2]*inv, fv[3]*inv);
            float4 w1 = make_float4(fv[4]*inv, fv[5]*inv, fv[6]*inv, fv[7]*inv);
            *(float4*)(S_at + n * 68 + m0)     = w0;
            *(float4*)(S_at + n * 68 + m0 + 4) = w1;
        }
        __syncthreads();
        // out[d][n] = sum_m v[d][m] * attn[n][m]  -> S_ll[ch0 slot]
        #pragma unroll
        for (int rep = 0; rep < 4; rep++) {
            int e = tid + rep * NTH;
            int d = e >> 6, nn = e & 63;
            const float4* vv = (const float4*)(S_v + (d << 6));
            const float4* pp = (const float4*)(S_at + nn * 68);
            float2 acc = make_float2(0.f, 0.f);
            #pragma unroll
            for (int m4 = 0; m4 < 16; m4++) {
                float4 a = vv[m4], p = pp[m4];
                acc = ffma2(make_float2(a.x, a.y), make_float2(p.x, p.y), acc);
                acc = ffma2(make_float2(a.z, a.w), make_float2(p.z, p.w), acc);
            }
            S_ll[((ch0 + d) << 6) + nn] = acc.x + acc.y;
        }
        __syncthreads();
    }

    // ================= Phase C: relu + 256x256 projection =================
    for (int i = tid; i < 16384; i += NTH) S_ll[i] = fmaxf(S_ll[i], 0.f);
    __syncthreads();
    {
        const int orow = tid >> 3;        // 0..63
        const int n0   = (tid & 7) << 3;  // 0..56
        float2 acc[4][4];
        #pragma unroll
        for (int a_ = 0; a_ < 4; a_++)
            #pragma unroll
            for (int b_ = 0; b_ < 4; b_++) acc[a_][b_] = make_float2(0.f, 0.f);

        for (int cb = 0; cb < 8; cb++) {
            // stage pre-reordered weight block: contiguous 8192 floats
            const float4* wsrc = (const float4*)(g_Wp + (cb << 13));
            #pragma unroll
            for (int r = 0; r < 4; r++) {
                int li = tid + r * NTH;     // 0..2047
                ((float4*)S_ws)[li] = wsrc[li];
            }
            __syncthreads();
            #pragma unroll 2
            for (int cc = 0; cc < 32; cc++) {
                int c = (cb << 5) + cc;
                const float4* ar = (const float4*)(S_ll + (c << 6) + n0);
                float4 A0 = ar[0], A1 = ar[1];
                float2 a0 = make_float2(A0.x, A0.y);
                float2 a1 = make_float2(A0.z, A0.w);
                float2 a2 = make_float2(A1.x, A1.y);
                float2 a3 = make_float2(A1.z, A1.w);
                float4 wv = *(const float4*)(S_ws + (cc << 8) + (orow << 2));
                const float ws[4] = {wv.x, wv.y, wv.z, wv.w};
                #pragma unroll
                for (int oo = 0; oo < 4; oo++) {
                    float2 w2 = make_float2(ws[oo], ws[oo]);
                    acc[oo][0] = ffma2(a0, w2, acc[oo][0]);
                    acc[oo][1] = ffma2(a1, w2, acc[oo][1]);
                    acc[oo][2] = ffma2(a2, w2, acc[oo][2]);
                    acc[oo][3] = ffma2(a3, w2, acc[oo][3]);
                }
            }
            __syncthreads();
        }
        #pragma unroll
        for (int oo = 0; oo < 4; oo++) {
            int o = orow + (oo << 6);
            float pb = pjb[o];
            float* dst = S_ll + (o << 6) + n0;
            dst[0] = acc[oo][0].x + pb; dst[1] = acc[oo][0].y + pb;
            dst[2] = acc[oo][1].x + pb; dst[3] = acc[oo][1].y + pb;
            dst[4] = acc[oo][2].x + pb; dst[5] = acc[oo][2].y + pb;
            dst[6] = acc[oo][3].x + pb; dst[7] = acc[oo][3].y + pb;
        }
    }
    __syncthreads();

    // ================= Phase D: inverse wavelet -> out =================
    for (int i = tid; i < 4096; i += NTH) S_iw[i] = iwtf[i];
    __syncthreads();
    {
        float* ob = out + (size_t)wb * (256u * 256u * 256u);
        #pragma unroll 4
        for (int rep = 0; rep < 16; rep++) {
            int u = tid + rep * NTH;
            int c = u >> 5;
            int i = (u >> 2) & 7;
            int k = u & 3;
            int o0 = (c << 6) + (i << 3) + (k << 1);
            const float* w = S_iw + (c << 4);
            float ll0 = S_ll[o0], ll1 = S_ll[o0 + 1];
            float2 lh = __half22float2(*(const __half2*)(S_lh + o0));
            float2 hl = __half22float2(*(const __half2*)(S_hl + o0));
            float2 hh = __half22float2(*(const __half2*)(S_hh + o0));
            float4 r0, r1;
            r0.x = ll0*w[0] + lh.x*w[4] + hl.x*w[8]  + hh.x*w[12];
            r0.y = ll0*w[1] + lh.x*w[5] + hl.x*w[9]  + hh.x*w[13];
            r0.z = ll1*w[0] + lh.y*w[4] + hl.y*w[8]  + hh.y*w[12];
            r0.w = ll1*w[1] + lh.y*w[5] + hl.y*w[9]  + hh.y*w[13];
            r1.x = ll0*w[2] + lh.x*w[6] + hl.x*w[10] + hh.x*w[14];
            r1.y = ll0*w[3] + lh.x*w[7] + hl.x*w[11] + hh.x*w[15];
            r1.z = ll1*w[2] + lh.y*w[6] + hl.y*w[10] + hh.y*w[14];
            r1.w = ll1*w[3] + lh.y*w[7] + hl.y*w[11] + hh.y*w[15];
            int gy = (wy << 4) + (i << 1);
            int gx = (wx << 4) + (k << 2);
            float* q_ = ob + (((c << 8) + gy) << 8) + gx;
            *(float4*)q_ = r0;
            *(float4*)(q_ + 256) = r1;
        }
    }
}

extern "C" void kernel_launch(void* const* d_in, const int* in_sizes, int n_in,
                              void* d_out, int out_size) {
    const float* x    = (const float*)d_in[0];
    const float* wtf  = (const float*)d_in[1];
    const float* iwtf = (const float*)d_in[2];
    const float* dww  = (const float*)d_in[3];
    const float* dwb  = (const float*)d_in[4];
    const float* pjw  = (const float*)d_in[5];
    const float* pjb  = (const float*)d_in[6];
    const float* atb  = (const float*)d_in[7];
    const int*   bix  = (const int*)d_in[8];
    float* o = (float*)d_out;
    (void)in_sizes; (void)n_in; (void)out_size;
    prep_kernel<<<256, 256>>>(pjw);
    cudaFuncSetAttribute(wwa_kernel, cudaFuncAttributeMaxDynamicSharedMemorySize, SMEM_BYTES);
    wwa_kernel<<<512, NTH, SMEM_BYTES>>>(x, wtf, iwtf, dww, dwb, pjb, atb, bix, o);
}

// round 3
// speedup vs baseline: 2.6884x; 1.1433x over previous
#include <cuda_runtime.h>
#include <cuda_fp16.h>

// WaveletWindowAttention fused kernel (R3): 1024 threads/CTA, 512 CTAs.
// vs R2: doubled warps for latency hiding, PV attn-row register caching with
// m-half partial sums, QK^T d-half split, vectorized v-copy, uint2 bias gather.

#define NTH 1024

__device__ float g_Wp[65536];   // reordered proj weights: [cb][cc][(o&63)*4 + (o>>6)]

__device__ __forceinline__ float2 ffma2(float2 a, float2 b, float2 c) {
    unsigned long long ua = *reinterpret_cast<unsigned long long*>(&a);
    unsigned long long ub = *reinterpret_cast<unsigned long long*>(&b);
    unsigned long long uc = *reinterpret_cast<unsigned long long*>(&c);
    unsigned long long ud;
    asm("fma.rn.f32x2 %0, %1, %2, %3;" : "=l"(ud) : "l"(ua), "l"(ub), "l"(uc));
    return *reinterpret_cast<float2*>(&ud);
}

__global__ void prep_kernel(const float* __restrict__ pjw) {
    int i = blockIdx.x * 256 + threadIdx.x;      // 65536 total
    int o = i >> 8, c = i & 255;
    g_Wp[((c >> 5) << 13) + ((c & 31) << 8) + ((o & 63) << 2) + (o >> 6)] =
        pjw[(o << 8) + c];
}

// ---- shared memory layout (bytes) ----
// S_ll f32 [256][64] @0 (65536)   S_lh/S_hl/S_hh f16 [256][64] @65536/98304/131072
// Z @163840:
//   S_q  f32[64][33]  Z+0      (8448)
//   S_at f32[64][68]  Z+8448   (17408)
//   S_v  f32[32][64]  Z+25856  (8192)
//   S_dw f32[800]     Z+34048  (3200)
//   S_db f32[32]      Z+37248  (128)
//   S_bi u8[4096]     Z+37376  (4096)
//   S_ab f32[512]     Z+41472  (2048)
//   aliases over Z (disjoint from S_dw..S_ab): S_wt f32[4096] (A),
//   S_ws f32[8192] (C), S_iw f32[4096] (D)
#define SMEM_BYTES 207360

__global__ void __launch_bounds__(NTH, 1)
wwa_kernel(const float* __restrict__ x,   const float* __restrict__ wtf,
           const float* __restrict__ iwtf,const float* __restrict__ dww,
           const float* __restrict__ dwb, const float* __restrict__ pjb,
           const float* __restrict__ atb, const int* __restrict__ bix,
           float* __restrict__ out)
{
    extern __shared__ unsigned char sm[];
    float*  S_ll = (float*)sm;
    __half* S_lh = (__half*)(sm + 65536);
    __half* S_hl = (__half*)(sm + 98304);
    __half* S_hh = (__half*)(sm + 131072);
    unsigned char* Z = sm + 163840;
    float* S_q  = (float*)Z;
    float* S_at = (float*)(Z + 8448);
    float* S_v  = (float*)(Z + 25856);
    float* S_dw = (float*)(Z + 34048);
    float* S_db = (float*)(Z + 37248);
    unsigned char* S_bi = Z + 37376;
    float* S_ab = (float*)(Z + 41472);
    float* S_wt = (float*)Z;
    float* S_ws = (float*)Z;
    float* S_iw = (float*)Z;

    const int tid  = threadIdx.x;
    const int widx = blockIdx.x;
    const int wb = widx >> 8;
    const int wy = (widx >> 4) & 15;
    const int wx = widx & 15;

    // ---- tables + head-0 depthwise weights ----
    for (int i = tid; i < 4096; i += NTH) S_wt[i] = wtf[i];
    for (int i = tid; i < 4096; i += NTH) S_bi[i] = (unsigned char)bix[i];
    for (int i = tid; i < 512;  i += NTH) S_ab[i] = atb[i];
    for (int i = tid; i < 800;  i += NTH) S_dw[i] = dww[i];
    if (tid < 32) S_db[tid] = dwb[tid];
    __syncthreads();

    // ================= Phase A: forward wavelet =================
    {
        const float* xb = x + (size_t)wb * (256u * 256u * 256u);
        #pragma unroll 4
        for (int rep = 0; rep < 8; rep++) {
            int u = tid + rep * NTH;        // (c, i, k)
            int c = u >> 5;
            int i = (u >> 2) & 7;
            int k = u & 3;
            int gy = (wy << 4) + (i << 1);
            int gx = (wx << 4) + (k << 2);
            const float* p = xb + (((c << 8) + gy) << 8) + gx;
            float4 a = *(const float4*)p;
            float4 b = *(const float4*)(p + 256);
            const float* w = S_wt + (c << 4);
            int o0 = (c << 6) + (i << 3) + (k << 1);
            float v0, v1;
            v0 = a.x*w[0] + a.y*w[1] + b.x*w[2] + b.y*w[3];
            v1 = a.z*w[0] + a.w*w[1] + b.z*w[2] + b.w*w[3];
            *(float2*)(S_ll + o0) = make_float2(v0, v1);
            v0 = a.x*w[4] + a.y*w[5] + b.x*w[6] + b.y*w[7];
            v1 = a.z*w[4] + a.w*w[5] + b.z*w[6] + b.w*w[7];
            *(__half2*)(S_lh + o0) = __floats2half2_rn(v0, v1);
            v0 = a.x*w[8] + a.y*w[9] + b.x*w[10] + b.y*w[11];
            v1 = a.z*w[8] + a.w*w[9] + b.z*w[10] + b.w*w[11];
            *(__half2*)(S_hl + o0) = __floats2half2_rn(v0, v1);
            v0 = a.x*w[12] + a.y*w[13] + b.x*w[14] + b.y*w[15];
            v1 = a.z*w[12] + a.w*w[13] + b.z*w[14] + b.w*w[15];
            *(__half2*)(S_hh + o0) = __floats2half2_rn(v0, v1);
        }
    }
    __syncthreads();

    // ================= Phase B: 8 sequential heads =================
    for (int hd = 0; hd < 8; hd++) {
        const int ch0 = hd << 5;

        // ---- sec1: q-conv + v-copy (uses S_dw/S_db loaded earlier) ----
        {   // v = original ll[ch0 slot] (+ prev head output at ch0-32 slot)
            int d  = tid >> 5;
            int m2 = (tid & 31) << 1;
            float2 v = *(const float2*)(S_ll + ((ch0 + d) << 6) + m2);
            if (hd > 0) {
                float2 pv = *(const float2*)(S_ll + ((ch0 - 32 + d) << 6) + m2);
                v.x += pv.x; v.y += pv.y;
            }
            *(float2*)(S_v + (d << 6) + m2) = v;
        }
        #pragma unroll
        for (int rep = 0; rep < 2; rep++) {   // depthwise 5x5 conv -> S_q[n][d]
            int e = tid + rep * NTH;
            int d = e >> 6, n = e & 63;
            int py = n >> 3, px = n & 7;
            float acc = S_db[d];
            const float* wd = S_dw + d * 25;
            const __half* lhr = S_lh + ((ch0 + d) << 6);
            #pragma unroll
            for (int uu = 0; uu < 5; uu++) {
                int yy = py + uu - 2;
                if ((unsigned)yy < 8u) {
                    #pragma unroll
                    for (int vv = 0; vv < 5; vv++) {
                        int xx = px + vv - 2;
                        if ((unsigned)xx < 8u)
                            acc += __half2float(lhr[(yy << 3) + xx]) * wd[uu * 5 + vv];
                    }
                }
            }
            S_q[n * 33 + d] = acc;
        }
        __syncthreads();

        // ---- sec2: QK^T d-half partials (+ prefetch next head dw) ----
        const int dh = tid >> 9;
        const int n  = (tid >> 3) & 63;
        const int m0 = (tid & 7) << 3;
        float2 v2[4];
        {
            v2[0] = v2[1] = v2[2] = v2[3] = make_float2(0.f, 0.f);
            const float* qr = S_q + n * 33 + (dh << 4);
            const int cbase = ch0 + (dh << 4);
            #pragma unroll 4
            for (int d = 0; d < 16; d++) {
                float qv = qr[d];
                float2 q2 = make_float2(qv, qv);
                uint4 kv = *(const uint4*)(S_hl + ((cbase + d) << 6) + m0);
                v2[0] = ffma2(q2, __half22float2(*(__half2*)&kv.x), v2[0]);
                v2[1] = ffma2(q2, __half22float2(*(__half2*)&kv.y), v2[1]);
                v2[2] = ffma2(q2, __half22float2(*(__half2*)&kv.z), v2[2]);
                v2[3] = ffma2(q2, __half22float2(*(__half2*)&kv.w), v2[3]);
            }
            if (dh == 0) {
                *(float4*)(S_at + n * 68 + m0)     = make_float4(v2[0].x, v2[0].y, v2[1].x, v2[1].y);
                *(float4*)(S_at + n * 68 + m0 + 4) = make_float4(v2[2].x, v2[2].y, v2[3].x, v2[3].y);
            }
        }
        if (hd < 7) {
            for (int i = tid; i < 800; i += NTH) S_dw[i] = dww[(hd + 1) * 800 + i];
            if (tid < 32) S_db[tid] = dwb[((hd + 1) << 5) + tid];
        }
        __syncthreads();

        // ---- sec3: combine + softmax (dh==1 threads) ----
        if (dh == 1) {
            float4 p0 = *(const float4*)(S_at + n * 68 + m0);
            float4 p1 = *(const float4*)(S_at + n * 68 + m0 + 4);
            float fv[8];
            uint2 bb = *(const uint2*)(S_bi + (n << 6) + m0);
            const float* ab = S_ab + (hd << 6);
            const float SC = 0.17677669529663687f;
            fv[0] = (v2[0].x + p0.x) * SC + ab[(bb.x)       & 255u];
            fv[1] = (v2[0].y + p0.y) * SC + ab[(bb.x >> 8)  & 255u];
            fv[2] = (v2[1].x + p0.z) * SC + ab[(bb.x >> 16) & 255u];
            fv[3] = (v2[1].y + p0.w) * SC + ab[(bb.x >> 24) & 255u];
            fv[4] = (v2[2].x + p1.x) * SC + ab[(bb.y)       & 255u];
            fv[5] = (v2[2].y + p1.y) * SC + ab[(bb.y >> 8)  & 255u];
            fv[6] = (v2[3].x + p1.z) * SC + ab[(bb.y >> 16) & 255u];
            fv[7] = (v2[3].y + p1.w) * SC + ab[(bb.y >> 24) & 255u];
            float mx = fv[0];
            #pragma unroll
            for (int j = 1; j < 8; j++) mx = fmaxf(mx, fv[j]);
            mx = fmaxf(mx, __shfl_xor_sync(0xffffffffu, mx, 1));
            mx = fmaxf(mx, __shfl_xor_sync(0xffffffffu, mx, 2));
            mx = fmaxf(mx, __shfl_xor_sync(0xffffffffu, mx, 4));
            float sum = 0.f;
            #pragma unroll
            for (int j = 0; j < 8; j++) { fv[j] = __expf(fv[j] - mx); sum += fv[j]; }
            sum += __shfl_xor_sync(0xffffffffu, sum, 1);
            sum += __shfl_xor_sync(0xffffffffu, sum, 2);
            sum += __shfl_xor_sync(0xffffffffu, sum, 4);
            float inv = 1.f / sum;
            *(float4*)(S_at + n * 68 + m0)     = make_float4(fv[0]*inv, fv[1]*inv, fv[2]*inv, fv[3]*inv);
            *(float4*)(S_at + n * 68 + m0 + 4) = make_float4(fv[4]*inv, fv[5]*inv, fv[6]*inv, fv[7]*inv);
        }
        __syncthreads();

        // ---- sec4: PV m-half partials; mh==0 stores to S_ll ----
        {
            const int mh = tid >> 9;            // m-half 0/1
            const int dg = (tid >> 6) & 7;      // 4-d group
            const int nn = tid & 63;
            const float* atr = S_at + nn * 68 + (mh << 5);
            const float* vb  = S_v + (mh << 5);
            float2 acc[4];
            acc[0] = acc[1] = acc[2] = acc[3] = make_float2(0.f, 0.f);
            #pragma unroll
            for (int mq = 0; mq < 2; mq++) {
                float4 p[4];
                #pragma unroll
                for (int j = 0; j < 4; j++) p[j] = *(const float4*)(atr + (mq << 4) + (j << 2));
                #pragma unroll
                for (int dd = 0; dd < 4; dd++) {
                    const float* vr = vb + (((dg << 2) + dd) << 6) + (mq << 4);
                    #pragma unroll
                    for (int j = 0; j < 4; j++) {
                        float4 vv = *(const float4*)(vr + (j << 2));
                        acc[dd] = ffma2(make_float2(vv.x, vv.y), make_float2(p[j].x, p[j].y), acc[dd]);
                        acc[dd] = ffma2(make_float2(vv.z, vv.w), make_float2(p[j].z, p[j].w), acc[dd]);
                    }
                }
            }
            float part[4];
            #pragma unroll
            for (int dd = 0; dd < 4; dd++) part[dd] = acc[dd].x + acc[dd].y;
            if (mh == 0) {
                #pragma unroll
                for (int dd = 0; dd < 4; dd++)
                    S_ll[((ch0 + (dg << 2) + dd) << 6) + nn] = part[dd];
            }
            __syncthreads();
            // ---- sec5: mh==1 adds its partial ----
            if (mh == 1) {
                #pragma unroll
                for (int dd = 0; dd < 4; dd++) {
                    int idx = ((ch0 + (dg << 2) + dd) << 6) + nn;
                    S_ll[idx] += part[dd];
                }
            }
            __syncthreads();
        }
    }

    // ================= Phase C: relu + 256x256 projection =================
    {
        float4* p4 = (float4*)S_ll;
        #pragma unroll
        for (int rep = 0; rep < 4; rep++) {
            int i = tid + rep * NTH;            // 4096 float4
            float4 v = p4[i];
            v.x = fmaxf(v.x, 0.f); v.y = fmaxf(v.y, 0.f);
            v.z = fmaxf(v.z, 0.f); v.w = fmaxf(v.w, 0.f);
            p4[i] = v;
        }
    }
    __syncthreads();
    {
        const int oq = tid >> 4;          // 0..63
        const int n0 = (tid & 15) << 2;   // 0..60 step 4
        float2 acc[4][2];
        #pragma unroll
        for (int a_ = 0; a_ < 4; a_++) { acc[a_][0] = make_float2(0.f,0.f); acc[a_][1] = make_float2(0.f,0.f); }

        for (int cb = 0; cb < 8; cb++) {
            const float4* wsrc = (const float4*)(g_Wp + (cb << 13));
            #pragma unroll
            for (int r = 0; r < 2; r++) ((float4*)S_ws)[tid + r * NTH] = wsrc[tid + r * NTH];
            __syncthreads();
            #pragma unroll 2
            for (int cc = 0; cc < 32; cc++) {
                int c = (cb << 5) + cc;
                float4 A = *(const float4*)(S_ll + (c << 6) + n0);
                float2 a0 = make_float2(A.x, A.y);
                float2 a1 = make_float2(A.z, A.w);
                float4 wv = *(const float4*)(S_ws + (cc << 8) + (oq << 2));
                const float ws[4] = {wv.x, wv.y, wv.z, wv.w};
                #pragma unroll
                for (int oo = 0; oo < 4; oo++) {
                    float2 w2 = make_float2(ws[oo], ws[oo]);
                    acc[oo][0] = ffma2(a0, w2, acc[oo][0]);
                    acc[oo][1] = ffma2(a1, w2, acc[oo][1]);
                }
            }
            __syncthreads();
        }
        #pragma unroll
        for (int oo = 0; oo < 4; oo++) {
            int o = oq + (oo << 6);
            float pb = pjb[o];
            *(float4*)(S_ll + (o << 6) + n0) =
                make_float4(acc[oo][0].x + pb, acc[oo][0].y + pb,
                            acc[oo][1].x + pb, acc[oo][1].y + pb);
        }
    }
    __syncthreads();

    // ================= Phase D: inverse wavelet -> out =================
    for (int i = tid; i < 4096; i += NTH) S_iw[i] = iwtf[i];
    __syncthreads();
    {
        float* ob = out + (size_t)wb * (256u * 256u * 256u);
        #pragma unroll 4
        for (int rep = 0; rep < 8; rep++) {
            int u = tid + rep * NTH;
            int c = u >> 5;
            int i = (u >> 2) & 7;
            int k = u & 3;
            int o0 = (c << 6) + (i << 3) + (k << 1);
            const float* w = S_iw + (c << 4);
            float2 llv = *(const float2*)(S_ll + o0);
            float2 lh = __half22float2(*(const __half2*)(S_lh + o0));
            float2 hl = __half22float2(*(const __half2*)(S_hl + o0));
            float2 hh = __half22float2(*(const __half2*)(S_hh + o0));
            float4 r0, r1;
            r0.x = llv.x*w[0] + lh.x*w[4] + hl.x*w[8]  + hh.x*w[12];
            r0.y = llv.x*w[1] + lh.x*w[5] + hl.x*w[9]  + hh.x*w[13];
            r0.z = llv.y*w[0] + lh.y*w[4] + hl.y*w[8]  + hh.y*w[12];
            r0.w = llv.y*w[1] + lh.y*w[5] + hl.y*w[9]  + hh.y*w[13];
            r1.x = llv.x*w[2] + lh.x*w[6] + hl.x*w[10] + hh.x*w[14];
            r1.y = llv.x*w[3] + lh.x*w[7] + hl.x*w[11] + hh.x*w[15];
            r1.z = llv.y*w[2] + lh.y*w[6] + hl.y*w[10] + hh.y*w[14];
            r1.w = llv.y*w[3] + lh.y*w[7] + hl.y*w[11] + hh.y*w[15];
            int gy = (wy << 4) + (i << 1);
            int gx = (wx << 4) + (k << 2);
            float* q_ = ob + (((c << 8) + gy) << 8) + gx;
            *(float4*)q_ = r0;
            *(float4*)(q_ + 256) = r1;
        }
    }
}

extern "C" void kernel_launch(void* const* d_in, const int* in_sizes, int n_in,
                              void* d_out, int out_size) {
    const float* x    = (const float*)d_in[0];
    const float* wtf  = (const float*)d_in[1];
    const float* iwtf = (const float*)d_in[2];
    const float* dww  = (const float*)d_in[3];
    const float* dwb  = (const float*)d_in[4];
    const float* pjw  = (const float*)d_in[5];
    const float* pjb  = (const float*)d_in[6];
    const float* atb  = (const float*)d_in[7];
    const int*   bix  = (const int*)d_in[8];
    float* o = (float*)d_out;
    (void)in_sizes; (void)n_in; (void)out_size;
    prep_kernel<<<256, 256>>>(pjw);
    cudaFuncSetAttribute(wwa_kernel, cudaFuncAttributeMaxDynamicSharedMemorySize, SMEM_BYTES);
    wwa_kernel<<<512, NTH, SMEM_BYTES>>>(x, wtf, iwtf, dww, dwb, pjb, atb, bix, o);
}

// round 5
// speedup vs baseline: 3.8394x; 1.4281x over previous
#include <cuda_runtime.h>
#include <cuda_fp16.h>
#include <cstdint>

// WaveletWindowAttention fused kernel (R5): 1024 threads/CTA, 512 CTAs.
// vs R3: phase-C projection via warp-level HMMA (mma.sync m16n8k16, fp16 in
// fp32 accum; weights pre-packed in fragment order, activations transposed to
// fp16 [n][c]); q-conv rewritten with half2 strip loads (2 outputs/thread).
// (tcgen05 is unavailable: harness compiles through compute_103 PTX.)

#define NTH 1024

__device__ __half g_WpH[65536];   // proj weights fp16 in HMMA A-fragment order

__device__ __forceinline__ float2 ffma2(float2 a, float2 b, float2 c) {
    unsigned long long ua = *reinterpret_cast<unsigned long long*>(&a);
    unsigned long long ub = *reinterpret_cast<unsigned long long*>(&b);
    unsigned long long uc = *reinterpret_cast<unsigned long long*>(&c);
    unsigned long long ud;
    asm("fma.rn.f32x2 %0, %1, %2, %3;" : "=l"(ud) : "l"(ua), "l"(ub), "l"(uc));
    return *reinterpret_cast<float2*>(&ud);
}

// prep: pjw[o][c] fp32 -> g_WpH in [mt(16)][ks(16)][lane(32)][aidx(8)] order
__global__ void prep_kernel(const float* __restrict__ pjw) {
    int i = blockIdx.x * 256 + threadIdx.x;   // 65536
    int o = i >> 8, c = i & 255;
    int mt = o >> 4, m = o & 15;
    int ks = c >> 4, k = c & 15;
    int lane = ((m & 7) << 2) | ((k & 7) >> 1);
    int aidx = (k & 1) | (((m >> 3) & 1) << 1) | ((k >> 3) << 2);
    g_WpH[(((((mt << 4) + ks) << 5) + lane) << 3) + aidx] =
        __float2half(pjw[(o << 8) + c]);
}

__device__ __forceinline__ void hmma16816(float* c4, const uint32_t* a4,
                                          uint32_t b0, uint32_t b1) {
    asm volatile(
        "mma.sync.aligned.m16n8k16.row.col.f32.f16.f16.f32 "
        "{%0,%1,%2,%3}, {%4,%5,%6,%7}, {%8,%9}, {%0,%1,%2,%3};"
        : "+f"(c4[0]), "+f"(c4[1]), "+f"(c4[2]), "+f"(c4[3])
        : "r"(a4[0]), "r"(a4[1]), "r"(a4[2]), "r"(a4[3]), "r"(b0), "r"(b1));
}

// ---- shared memory layout (bytes) ----
// S_ll f32 [256][64] @0 (65536)   S_lh/S_hl/S_hh f16 [256][64] @65536/98304/131072
// Z @163840 (43520 B):
//   S_q  f32[64][33]  Z+0      | S_at f32[64][68] Z+8448 | S_v f32[32][64] Z+25856
//   S_dw f32[800]     Z+34048  | S_db f32[32] Z+37248 | S_bi u8[4096] Z+37376
//   S_ab f32[512]     Z+41472
//   aliases on Z: S_wt (A), actT __half[64][264] (C, 33792 B), S_iw (D)
#define SMEM_BYTES 207360

__global__ void __launch_bounds__(NTH, 1)
wwa_kernel(const float* __restrict__ x,   const float* __restrict__ wtf,
           const float* __restrict__ iwtf,const float* __restrict__ dww,
           const float* __restrict__ dwb, const float* __restrict__ pjb,
           const float* __restrict__ atb, const int* __restrict__ bix,
           float* __restrict__ out)
{
    extern __shared__ unsigned char sm[];
    float*  S_ll = (float*)sm;
    __half* S_lh = (__half*)(sm + 65536);
    __half* S_hl = (__half*)(sm + 98304);
    __half* S_hh = (__half*)(sm + 131072);
    unsigned char* Z = sm + 163840;
    float* S_q  = (float*)Z;
    float* S_at = (float*)(Z + 8448);
    float* S_v  = (float*)(Z + 25856);
    float* S_dw = (float*)(Z + 34048);
    float* S_db = (float*)(Z + 37248);
    unsigned char* S_bi = Z + 37376;
    float* S_ab = (float*)(Z + 41472);
    float* S_wt = (float*)Z;
    __half* S_actT = (__half*)Z;          // [64][264]
    float* S_iw = (float*)Z;

    const int tid  = threadIdx.x;
    const int wid  = tid >> 5;
    const int lane = tid & 31;
    const int widx = blockIdx.x;
    const int wb = widx >> 8;
    const int wy = (widx >> 4) & 15;
    const int wx = widx & 15;

    // ---- tables + head-0 dw weights ----
    for (int i = tid; i < 4096; i += NTH) S_wt[i] = wtf[i];
    for (int i = tid; i < 4096; i += NTH) S_bi[i] = (unsigned char)bix[i];
    for (int i = tid; i < 512;  i += NTH) S_ab[i] = atb[i];
    for (int i = tid; i < 800;  i += NTH) S_dw[i] = dww[i];
    if (tid < 32) S_db[tid] = dwb[tid];
    __syncthreads();

    // ================= Phase A: forward wavelet =================
    {
        const float* xb = x + (size_t)wb * (256u * 256u * 256u);
        #pragma unroll 4
        for (int rep = 0; rep < 8; rep++) {
            int u = tid + rep * NTH;        // (c, i, k)
            int c = u >> 5;
            int i = (u >> 2) & 7;
            int k = u & 3;
            int gy = (wy << 4) + (i << 1);
            int gx = (wx << 4) + (k << 2);
            const float* p = xb + (((c << 8) + gy) << 8) + gx;
            float4 a = *(const float4*)p;
            float4 b = *(const float4*)(p + 256);
            const float* w = S_wt + (c << 4);
            int o0 = (c << 6) + (i << 3) + (k << 1);
            float v0, v1;
            v0 = a.x*w[0] + a.y*w[1] + b.x*w[2] + b.y*w[3];
            v1 = a.z*w[0] + a.w*w[1] + b.z*w[2] + b.w*w[3];
            *(float2*)(S_ll + o0) = make_float2(v0, v1);
            v0 = a.x*w[4] + a.y*w[5] + b.x*w[6] + b.y*w[7];
            v1 = a.z*w[4] + a.w*w[5] + b.z*w[6] + b.w*w[7];
            *(__half2*)(S_lh + o0) = __floats2half2_rn(v0, v1);
            v0 = a.x*w[8] + a.y*w[9] + b.x*w[10] + b.y*w[11];
            v1 = a.z*w[8] + a.w*w[9] + b.z*w[10] + b.w*w[11];
            *(__half2*)(S_hl + o0) = __floats2half2_rn(v0, v1);
            v0 = a.x*w[12] + a.y*w[13] + b.x*w[14] + b.y*w[15];
            v1 = a.z*w[12] + a.w*w[13] + b.z*w[14] + b.w*w[15];
            *(__half2*)(S_hh + o0) = __floats2half2_rn(v0, v1);
        }
    }
    __syncthreads();

    // ================= Phase B: 8 sequential heads =================
    for (int hd = 0; hd < 8; hd++) {
        const int ch0 = hd << 5;

        // ---- sec1: v-copy + q-conv (half2 strip: 2 outputs/thread) ----
        {
            int d  = tid >> 5;
            int m2 = (tid & 31) << 1;
            float2 v = *(const float2*)(S_ll + ((ch0 + d) << 6) + m2);
            if (hd > 0) {
                float2 pv = *(const float2*)(S_ll + ((ch0 - 32 + d) << 6) + m2);
                v.x += pv.x; v.y += pv.y;
            }
            *(float2*)(S_v + (d << 6) + m2) = v;
        }
        {
            int d   = tid >> 5;            // warp-uniform channel
            int s   = tid & 31;
            int py  = s >> 2;
            int px0 = (s & 3) << 1;
            int base = px0 >> 1;           // 0..3
            float a0 = S_db[d], a1 = a0;
            const float* wd = S_dw + d * 25;
            const __half2* row = (const __half2*)(S_lh + ((ch0 + d) << 6));
            #pragma unroll
            for (int uu = 0; uu < 5; uu++) {
                int yy = py + uu - 2;
                if ((unsigned)yy < 8u) {
                    const __half2* r = row + (yy << 2);
                    const float* w = wd + uu * 5;
                    if (base >= 1) {
                        float2 h = __half22float2(r[base - 1]);
                        a0 += h.x * w[0] + h.y * w[1];
                        a1 += h.y * w[0];
                    }
                    {
                        float2 h = __half22float2(r[base]);
                        a0 += h.x * w[2] + h.y * w[3];
                        a1 += h.x * w[1] + h.y * w[2];
                    }
                    if (base <= 2) {
                        float2 h = __half22float2(r[base + 1]);
                        a0 += h.x * w[4];
                        a1 += h.x * w[3] + h.y * w[4];
                    }
                }
            }
            int n = (py << 3) + px0;
            S_q[n * 33 + d]       = a0;
            S_q[(n + 1) * 33 + d] = a1;
        }
        __syncthreads();

        // ---- sec2: QK^T d-half partials (+ prefetch next head dw) ----
        const int dh = tid >> 9;
        const int n  = (tid >> 3) & 63;
        const int m0 = (tid & 7) << 3;
        float2 v2[4];
        {
            v2[0] = v2[1] = v2[2] = v2[3] = make_float2(0.f, 0.f);
            const float* qr = S_q + n * 33 + (dh << 4);
            const int cbase = ch0 + (dh << 4);
            #pragma unroll 4
            for (int d = 0; d < 16; d++) {
                float qv = qr[d];
                float2 q2 = make_float2(qv, qv);
                uint4 kv = *(const uint4*)(S_hl + ((cbase + d) << 6) + m0);
                v2[0] = ffma2(q2, __half22float2(*(__half2*)&kv.x), v2[0]);
                v2[1] = ffma2(q2, __half22float2(*(__half2*)&kv.y), v2[1]);
                v2[2] = ffma2(q2, __half22float2(*(__half2*)&kv.z), v2[2]);
                v2[3] = ffma2(q2, __half22float2(*(__half2*)&kv.w), v2[3]);
            }
            if (dh == 0) {
                *(float4*)(S_at + n * 68 + m0)     = make_float4(v2[0].x, v2[0].y, v2[1].x, v2[1].y);
                *(float4*)(S_at + n * 68 + m0 + 4) = make_float4(v2[2].x, v2[2].y, v2[3].x, v2[3].y);
            }
        }
        if (hd < 7) {
            for (int i = tid; i < 800; i += NTH) S_dw[i] = dww[(hd + 1) * 800 + i];
            if (tid < 32) S_db[tid] = dwb[((hd + 1) << 5) + tid];
        }
        __syncthreads();

        // ---- sec3: combine + softmax (dh==1 threads) ----
        if (dh == 1) {
            float4 p0 = *(const float4*)(S_at + n * 68 + m0);
            float4 p1 = *(const float4*)(S_at + n * 68 + m0 + 4);
            float fv[8];
            uint2 bb = *(const uint2*)(S_bi + (n << 6) + m0);
            const float* ab = S_ab + (hd << 6);
            const float SC = 0.17677669529663687f;
            fv[0] = (v2[0].x + p0.x) * SC + ab[(bb.x)       & 255u];
            fv[1] = (v2[0].y + p0.y) * SC + ab[(bb.x >> 8)  & 255u];
            fv[2] = (v2[1].x + p0.z) * SC + ab[(bb.x >> 16) & 255u];
            fv[3] = (v2[1].y + p0.w) * SC + ab[(bb.x >> 24) & 255u];
            fv[4] = (v2[2].x + p1.x) * SC + ab[(bb.y)       & 255u];
            fv[5] = (v2[2].y + p1.y) * SC + ab[(bb.y >> 8)  & 255u];
            fv[6] = (v2[3].x + p1.z) * SC + ab[(bb.y >> 16) & 255u];
            fv[7] = (v2[3].y + p1.w) * SC + ab[(bb.y >> 24) & 255u];
            float mx = fv[0];
            #pragma unroll
            for (int j = 1; j < 8; j++) mx = fmaxf(mx, fv[j]);
            mx = fmaxf(mx, __shfl_xor_sync(0xffffffffu, mx, 1));
            mx = fmaxf(mx, __shfl_xor_sync(0xffffffffu, mx, 2));
            mx = fmaxf(mx, __shfl_xor_sync(0xffffffffu, mx, 4));
            float sum = 0.f;
            #pragma unroll
            for (int j = 0; j < 8; j++) { fv[j] = __expf(fv[j] - mx); sum += fv[j]; }
            sum += __shfl_xor_sync(0xffffffffu, sum, 1);
            sum += __shfl_xor_sync(0xffffffffu, sum, 2);
            sum += __shfl_xor_sync(0xffffffffu, sum, 4);
            float inv = 1.f / sum;
            *(float4*)(S_at + n * 68 + m0)     = make_float4(fv[0]*inv, fv[1]*inv, fv[2]*inv, fv[3]*inv);
            *(float4*)(S_at + n * 68 + m0 + 4) = make_float4(fv[4]*inv, fv[5]*inv, fv[6]*inv, fv[7]*inv);
        }
        __syncthreads();

        // ---- sec4/5: PV m-half partials ----
        {
            const int mh = tid >> 9;
            const int dg = (tid >> 6) & 7;
            const int nn = tid & 63;
            const float* atr = S_at + nn * 68 + (mh << 5);
            const float* vb  = S_v + (mh << 5);
            float2 acc[4];
            acc[0] = acc[1] = acc[2] = acc[3] = make_float2(0.f, 0.f);
            #pragma unroll
            for (int mq = 0; mq < 2; mq++) {
                float4 p[4];
                #pragma unroll
                for (int j = 0; j < 4; j++) p[j] = *(const float4*)(atr + (mq << 4) + (j << 2));
                #pragma unroll
                for (int dd = 0; dd < 4; dd++) {
                    const float* vr = vb + (((dg << 2) + dd) << 6) + (mq << 4);
                    #pragma unroll
                    for (int j = 0; j < 4; j++) {
                        float4 vv = *(const float4*)(vr + (j << 2));
                        acc[dd] = ffma2(make_float2(vv.x, vv.y), make_float2(p[j].x, p[j].y), acc[dd]);
                        acc[dd] = ffma2(make_float2(vv.z, vv.w), make_float2(p[j].z, p[j].w), acc[dd]);
                    }
                }
            }
            float part[4];
            #pragma unroll
            for (int dd = 0; dd < 4; dd++) part[dd] = acc[dd].x + acc[dd].y;
            if (mh == 0) {
                #pragma unroll
                for (int dd = 0; dd < 4; dd++)
                    S_ll[((ch0 + (dg << 2) + dd) << 6) + nn] = part[dd];
            }
            __syncthreads();
            if (mh == 1) {
                #pragma unroll
                for (int dd = 0; dd < 4; dd++)
                    S_ll[((ch0 + (dg << 2) + dd) << 6) + nn] += part[dd];
            }
            __syncthreads();
        }
    }

    // ===== Phase C: relu + fp16 transpose + HMMA projection =====
    {
        // actT[n][c] fp16 (stride 264) = relu(S_ll[c][n])
        int nn = tid & 63;
        int c0 = (tid >> 6) << 4;         // 16-channel chunk
        __half2 hh[8];
        #pragma unroll
        for (int j = 0; j < 8; j++) {
            float f0 = fmaxf(S_ll[((c0 + 2*j    ) << 6) + nn], 0.f);
            float f1 = fmaxf(S_ll[((c0 + 2*j + 1) << 6) + nn], 0.f);
            hh[j] = __floats2half2_rn(f0, f1);
        }
        __syncthreads();                   // everyone done reading S_ll
        *(uint4*)(S_actT + nn * 264 + c0)     = *(uint4*)&hh[0];
        *(uint4*)(S_actT + nn * 264 + c0 + 8) = *(uint4*)&hh[4];
    }
    __syncthreads();
    {
        const int mt = wid >> 1;          // 16 m-tiles of 16 rows
        const int nh = wid & 1;           // n-half: cols nh*32 .. +32
        const int g  = lane >> 2;
        const int t  = lane & 3;
        float acc[4][4];
        #pragma unroll
        for (int i = 0; i < 4; i++)
            #pragma unroll
            for (int j = 0; j < 4; j++) acc[i][j] = 0.f;

        const uint4* afrag = (const uint4*)g_WpH + (mt << 9) + lane;
        const __half* bbase = S_actT + ((nh << 5) + g) * 264 + (t << 1);
        #pragma unroll 4
        for (int ks = 0; ks < 16; ks++) {
            uint4 a = afrag[ks << 5];
            const __half* bp = bbase + (ks << 4);
            #pragma unroll
            for (int ntl = 0; ntl < 4; ntl++) {
                uint32_t b0 = *(const uint32_t*)(bp + ntl * 8 * 264);
                uint32_t b1 = *(const uint32_t*)(bp + ntl * 8 * 264 + 8);
                hmma16816(acc[ntl], (const uint32_t*)&a, b0, b1);
            }
        }
        // epilogue: bias + store to S_ll
        int o0 = (mt << 4) + g;
        float pb0 = pjb[o0], pb1 = pjb[o0 + 8];
        int ncol = (nh << 5) + (t << 1);
        #pragma unroll
        for (int ntl = 0; ntl < 4; ntl++) {
            int nc = ncol + (ntl << 3);
            *(float2*)(S_ll + (o0 << 6) + nc) =
                make_float2(acc[ntl][0] + pb0, acc[ntl][1] + pb0);
            *(float2*)(S_ll + ((o0 + 8) << 6) + nc) =
                make_float2(acc[ntl][2] + pb1, acc[ntl][3] + pb1);
        }
    }
    __syncthreads();

    // ================= Phase D: inverse wavelet -> out =================
    for (int i = tid; i < 4096; i += NTH) S_iw[i] = iwtf[i];
    __syncthreads();
    {
        float* ob = out + (size_t)wb * (256u * 256u * 256u);
        #pragma unroll 4
        for (int rep = 0; rep < 8; rep++) {
            int u = tid + rep * NTH;
            int c = u >> 5;
            int i = (u >> 2) & 7;
            int k = u & 3;
            int o0 = (c << 6) + (i << 3) + (k << 1);
            const float* w = S_iw + (c << 4);
            float2 llv = *(const float2*)(S_ll + o0);
            float2 lh = __half22float2(*(const __half2*)(S_lh + o0));
            float2 hl = __half22float2(*(const __half2*)(S_hl + o0));
            float2 hh = __half22float2(*(const __half2*)(S_hh + o0));
            float4 r0, r1;
            r0.x = llv.x*w[0] + lh.x*w[4] + hl.x*w[8]  + hh.x*w[12];
            r0.y = llv.x*w[1] + lh.x*w[5] + hl.x*w[9]  + hh.x*w[13];
            r0.z = llv.y*w[0] + lh.y*w[4] + hl.y*w[8]  + hh.y*w[12];
            r0.w = llv.y*w[1] + lh.y*w[5] + hl.y*w[9]  + hh.y*w[13];
            r1.x = llv.x*w[2] + lh.x*w[6] + hl.x*w[10] + hh.x*w[14];
            r1.y = llv.x*w[3] + lh.x*w[7] + hl.x*w[11] + hh.x*w[15];
            r1.z = llv.y*w[2] + lh.y*w[6] + hl.y*w[10] + hh.y*w[14];
            r1.w = llv.y*w[3] + lh.y*w[7] + hl.y*w[11] + hh.y*w[15];
            int gy = (wy << 4) + (i << 1);
            int gx = (wx << 4) + (k << 2);
            float* q_ = ob + (((c << 8) + gy) << 8) + gx;
            *(float4*)q_ = r0;
            *(float4*)(q_ + 256) = r1;
        }
    }
}

extern "C" void kernel_launch(void* const* d_in, const int* in_sizes, int n_in,
                              void* d_out, int out_size) {
    const float* x    = (const float*)d_in[0];
    const float* wtf  = (const float*)d_in[1];
    const float* iwtf = (const float*)d_in[2];
    const float* dww  = (const float*)d_in[3];
    const float* dwb  = (const float*)d_in[4];
    const float* pjw  = (const float*)d_in[5];
    const float* pjb  = (const float*)d_in[6];
    const float* atb  = (const float*)d_in[7];
    const int*   bix  = (const int*)d_in[8];
    float* o = (float*)d_out;
    (void)in_sizes; (void)n_in; (void)out_size;
    prep_kernel<<<256, 256>>>(pjw);
    cudaFuncSetAttribute(wwa_kernel, cudaFuncAttributeMaxDynamicSharedMemorySize, SMEM_BYTES);
    wwa_kernel<<<512, NTH, SMEM_BYTES>>>(x, wtf, iwtf, dww, dwb, pjb, atb, bix, o);
}

// round 6
// speedup vs baseline: 4.0877x; 1.0647x over previous
#include <cuda_runtime.h>
#include <cuda_fp16.h>
#include <cstdint>

// WaveletWindowAttention fused kernel (R6): 1024 threads/CTA, 512 CTAs.
// vs R5: phase B restructured into 2 batches of 4 heads:
//   B1a: q-conv for all 128 batch channels at full width -> Q fp16 [n][136]
//   B1b: QK^T + bias + softmax fused in registers for 4 heads -> P fp16 [4][64][72]
//   B2:  per head only v-add + PV (fp16 attn, 4d x 1nn tile, 512 threads)
// Phase C projection stays HMMA (mma.sync m16n8k16).

#define NTH 1024
#define QSTR 136          // Q row stride in halves
#define PSTR 72           // P row stride in halves
#define PHEAD 4608        // 64*72 halves per head

__device__ __half g_WpH[65536];   // proj weights fp16 in HMMA A-fragment order

__device__ __forceinline__ float2 ffma2(float2 a, float2 b, float2 c) {
    unsigned long long ua = *reinterpret_cast<unsigned long long*>(&a);
    unsigned long long ub = *reinterpret_cast<unsigned long long*>(&b);
    unsigned long long uc = *reinterpret_cast<unsigned long long*>(&c);
    unsigned long long ud;
    asm("fma.rn.f32x2 %0, %1, %2, %3;" : "=l"(ud) : "l"(ua), "l"(ub), "l"(uc));
    return *reinterpret_cast<float2*>(&ud);
}

// prep: pjw[o][c] fp32 -> g_WpH in [mt(16)][ks(16)][lane(32)][aidx(8)] order
__global__ void prep_kernel(const float* __restrict__ pjw) {
    int i = blockIdx.x * 256 + threadIdx.x;   // 65536
    int o = i >> 8, c = i & 255;
    int mt = o >> 4, m = o & 15;
    int ks = c >> 4, k = c & 15;
    int lane = ((m & 7) << 2) | ((k & 7) >> 1);
    int aidx = (k & 1) | (((m >> 3) & 1) << 1) | ((k >> 3) << 2);
    g_WpH[(((((mt << 4) + ks) << 5) + lane) << 3) + aidx] =
        __float2half(pjw[(o << 8) + c]);
}

__device__ __forceinline__ void hmma16816(float* c4, const uint32_t* a4,
                                          uint32_t b0, uint32_t b1) {
    asm volatile(
        "mma.sync.aligned.m16n8k16.row.col.f32.f16.f16.f32 "
        "{%0,%1,%2,%3}, {%4,%5,%6,%7}, {%8,%9}, {%0,%1,%2,%3};"
        : "+f"(c4[0]), "+f"(c4[1]), "+f"(c4[2]), "+f"(c4[3])
        : "r"(a4[0]), "r"(a4[1]), "r"(a4[2]), "r"(a4[3]), "r"(b0), "r"(b1));
}

// ---- shared memory layout (bytes) ----
// S_ll f32 [256][64] @0 (65536)
// S_lh f16 [256][64] @65536 (32768)
// S_hl f16 [256][64] @98304 (32768)
// S_hh f16 [256][64] @131072 (32768)
// P    f16 [4][64][72] @163840 (36864)  aliases (timeline-disjoint):
//        S_wt f32[4096] (phase A), S_dw f32[3200]+S_db f32[128] (batch start,
//        dead after B1a; P written in B1b), actT f16[64][264] (phase C),
//        S_iw f32[4096] (phase D)
// Q    f16 [64][136] @200704 (17408)
// S_v  f32 [32][64]  @218112 (8192)
// S_bi u8  [4096]    @226304 (4096)
// S_ab f32 [512]     @230400 (2048)   end 232448
#define SMEM_BYTES 232448

__global__ void __launch_bounds__(NTH, 1)
wwa_kernel(const float* __restrict__ x,   const float* __restrict__ wtf,
           const float* __restrict__ iwtf,const float* __restrict__ dww,
           const float* __restrict__ dwb, const float* __restrict__ pjb,
           const float* __restrict__ atb, const int* __restrict__ bix,
           float* __restrict__ out)
{
    extern __shared__ unsigned char sm[];
    float*  S_ll = (float*)sm;
    __half* S_lh = (__half*)(sm + 65536);
    __half* S_hl = (__half*)(sm + 98304);
    __half* S_hh = (__half*)(sm + 131072);
    __half* P    = (__half*)(sm + 163840);
    float*  S_wt = (float*)(sm + 163840);
    float*  S_dw = (float*)(sm + 163840);
    float*  S_db = (float*)(sm + 163840 + 12800);
    __half* S_actT = (__half*)(sm + 163840);
    float*  S_iw = (float*)(sm + 163840);
    __half* Q    = (__half*)(sm + 200704);
    float*  S_v  = (float*)(sm + 218112);
    unsigned char* S_bi = sm + 226304;
    float*  S_ab = (float*)(sm + 230400);

    const int tid  = threadIdx.x;
    const int wid  = tid >> 5;
    const int lane = tid & 31;
    const int widx = blockIdx.x;
    const int wb = widx >> 8;
    const int wy = (widx >> 4) & 15;
    const int wx = widx & 15;

    // ---- init tables ----
    for (int i = tid; i < 4096; i += NTH) S_wt[i] = wtf[i];
    for (int i = tid; i < 4096; i += NTH) S_bi[i] = (unsigned char)bix[i];
    for (int i = tid; i < 512;  i += NTH) S_ab[i] = atb[i];
    __syncthreads();

    // ================= Phase A: forward wavelet =================
    {
        const float* xb = x + (size_t)wb * (256u * 256u * 256u);
        #pragma unroll 4
        for (int rep = 0; rep < 8; rep++) {
            int u = tid + rep * NTH;        // (c, i, k)
            int c = u >> 5;
            int i = (u >> 2) & 7;
            int k = u & 3;
            int gy = (wy << 4) + (i << 1);
            int gx = (wx << 4) + (k << 2);
            const float* p = xb + (((c << 8) + gy) << 8) + gx;
            float4 a = *(const float4*)p;
            float4 b = *(const float4*)(p + 256);
            const float* w = S_wt + (c << 4);
            int o0 = (c << 6) + (i << 3) + (k << 1);
            float v0, v1;
            v0 = a.x*w[0] + a.y*w[1] + b.x*w[2] + b.y*w[3];
            v1 = a.z*w[0] + a.w*w[1] + b.z*w[2] + b.w*w[3];
            *(float2*)(S_ll + o0) = make_float2(v0, v1);
            v0 = a.x*w[4] + a.y*w[5] + b.x*w[6] + b.y*w[7];
            v1 = a.z*w[4] + a.w*w[5] + b.z*w[6] + b.w*w[7];
            *(__half2*)(S_lh + o0) = __floats2half2_rn(v0, v1);
            v0 = a.x*w[8] + a.y*w[9] + b.x*w[10] + b.y*w[11];
            v1 = a.z*w[8] + a.w*w[9] + b.z*w[10] + b.w*w[11];
            *(__half2*)(S_hl + o0) = __floats2half2_rn(v0, v1);
            v0 = a.x*w[12] + a.y*w[13] + b.x*w[14] + b.y*w[15];
            v1 = a.z*w[12] + a.w*w[13] + b.z*w[14] + b.w*w[15];
            *(__half2*)(S_hh + o0) = __floats2half2_rn(v0, v1);
        }
    }
    __syncthreads();

    // ================= Phase B: 2 batches of 4 heads =================
    for (int bb = 0; bb < 2; bb++) {
        // ---- stage depthwise weights for this batch (aliases P; dead after B1a) ----
        for (int i = tid; i < 3200; i += NTH) S_dw[i] = dww[bb * 3200 + i];
        if (tid < 128) S_db[tid] = dwb[(bb << 7) + tid];
        __syncthreads();

        // ---- B1a: q-conv for 128 channels -> Q[n][cl] fp16 ----
        #pragma unroll
        for (int rep = 0; rep < 4; rep++) {
            int e  = tid + rep * NTH;      // 4096 strips
            int cl = e >> 5;               // 0..127 warp-uniform
            int s  = e & 31;
            int py = s >> 2;
            int px0 = (s & 3) << 1;
            int base = px0 >> 1;           // 0..3
            float a0 = S_db[cl], a1 = a0;
            const float* wd = S_dw + cl * 25;
            const __half2* row = (const __half2*)(S_lh + (((bb << 7) + cl) << 6));
            #pragma unroll
            for (int uu = 0; uu < 5; uu++) {
                int yy = py + uu - 2;
                if ((unsigned)yy < 8u) {
                    const __half2* r = row + (yy << 2);
                    const float* w = wd + uu * 5;
                    if (base >= 1) {
                        float2 h = __half22float2(r[base - 1]);
                        a0 += h.x * w[0] + h.y * w[1];
                        a1 += h.y * w[0];
                    }
                    {
                        float2 h = __half22float2(r[base]);
                        a0 += h.x * w[2] + h.y * w[3];
                        a1 += h.x * w[1] + h.y * w[2];
                    }
                    if (base <= 2) {
                        float2 h = __half22float2(r[base + 1]);
                        a0 += h.x * w[4];
                        a1 += h.x * w[3] + h.y * w[4];
                    }
                }
            }
            int n = (py << 3) + px0;
            Q[n * QSTR + cl]       = __float2half(a0);
            Q[(n + 1) * QSTR + cl] = __float2half(a1);
        }
        __syncthreads();

        // ---- B1b: QK^T + bias + softmax for 4 heads -> P (overwrites dw) ----
        #pragma unroll
        for (int rep = 0; rep < 2; rep++) {
            int e  = tid + rep * NTH;      // 2048 slots (hl, n, m0)
            int m0 = (e & 7) << 3;
            int n  = (e >> 3) & 63;
            int hl = e >> 9;               // 0..3 warp-uniform
            // q row (32 halves)
            uint4 qq[4];
            const uint4* qp = (const uint4*)(Q + n * QSTR + (hl << 5));
            qq[0] = qp[0]; qq[1] = qp[1]; qq[2] = qp[2]; qq[3] = qp[3];
            const __half2* qh = (const __half2*)qq;
            float2 v2[4];
            v2[0] = v2[1] = v2[2] = v2[3] = make_float2(0.f, 0.f);
            const __half* kb = S_hl + (((bb << 7) + (hl << 5)) << 6) + m0;
            #pragma unroll
            for (int d2 = 0; d2 < 16; d2++) {
                float2 qf = __half22float2(qh[d2]);
                uint4 kv0 = *(const uint4*)(kb + ((d2 * 2) << 6));
                float2 qx = make_float2(qf.x, qf.x);
                v2[0] = ffma2(qx, __half22float2(*(__half2*)&kv0.x), v2[0]);
                v2[1] = ffma2(qx, __half22float2(*(__half2*)&kv0.y), v2[1]);
                v2[2] = ffma2(qx, __half22float2(*(__half2*)&kv0.z), v2[2]);
                v2[3] = ffma2(qx, __half22float2(*(__half2*)&kv0.w), v2[3]);
                uint4 kv1 = *(const uint4*)(kb + ((d2 * 2 + 1) << 6));
                float2 qy = make_float2(qf.y, qf.y);
                v2[0] = ffma2(qy, __half22float2(*(__half2*)&kv1.x), v2[0]);
                v2[1] = ffma2(qy, __half22float2(*(__half2*)&kv1.y), v2[1]);
                v2[2] = ffma2(qy, __half22float2(*(__half2*)&kv1.z), v2[2]);
                v2[3] = ffma2(qy, __half22float2(*(__half2*)&kv1.w), v2[3]);
            }
            float fv[8];
            uint2 bbv = *(const uint2*)(S_bi + (n << 6) + m0);
            const float* ab = S_ab + (((bb << 2) + hl) << 6);
            const float SC = 0.17677669529663687f;
            fv[0] = v2[0].x * SC + ab[(bbv.x)       & 255u];
            fv[1] = v2[0].y * SC + ab[(bbv.x >> 8)  & 255u];
            fv[2] = v2[1].x * SC + ab[(bbv.x >> 16) & 255u];
            fv[3] = v2[1].y * SC + ab[(bbv.x >> 24) & 255u];
            fv[4] = v2[2].x * SC + ab[(bbv.y)       & 255u];
            fv[5] = v2[2].y * SC + ab[(bbv.y >> 8)  & 255u];
            fv[6] = v2[3].x * SC + ab[(bbv.y >> 16) & 255u];
            fv[7] = v2[3].y * SC + ab[(bbv.y >> 24) & 255u];
            float mx = fv[0];
            #pragma unroll
            for (int j = 1; j < 8; j++) mx = fmaxf(mx, fv[j]);
            mx = fmaxf(mx, __shfl_xor_sync(0xffffffffu, mx, 1));
            mx = fmaxf(mx, __shfl_xor_sync(0xffffffffu, mx, 2));
            mx = fmaxf(mx, __shfl_xor_sync(0xffffffffu, mx, 4));
            float sum = 0.f;
            #pragma unroll
            for (int j = 0; j < 8; j++) { fv[j] = __expf(fv[j] - mx); sum += fv[j]; }
            sum += __shfl_xor_sync(0xffffffffu, sum, 1);
            sum += __shfl_xor_sync(0xffffffffu, sum, 2);
            sum += __shfl_xor_sync(0xffffffffu, sum, 4);
            float inv = 1.f / sum;
            uint4 pk;
            *(__half2*)&pk.x = __floats2half2_rn(fv[0]*inv, fv[1]*inv);
            *(__half2*)&pk.y = __floats2half2_rn(fv[2]*inv, fv[3]*inv);
            *(__half2*)&pk.z = __floats2half2_rn(fv[4]*inv, fv[5]*inv);
            *(__half2*)&pk.w = __floats2half2_rn(fv[6]*inv, fv[7]*inv);
            *(uint4*)(P + hl * PHEAD + n * PSTR + m0) = pk;
        }
        __syncthreads();

        // ---- B2: 4 sequential heads (v-add + PV only) ----
        for (int hl = 0; hl < 4; hl++) {
            int hd  = (bb << 2) + hl;
            int ch0 = hd << 5;
            {   // v = ll[ch0 slot] (+ prev head output)
                int d  = tid >> 5;
                int m2 = (tid & 31) << 1;
                float2 v = *(const float2*)(S_ll + ((ch0 + d) << 6) + m2);
                if (hd > 0) {
                    float2 pv = *(const float2*)(S_ll + ((ch0 - 32 + d) << 6) + m2);
                    v.x += pv.x; v.y += pv.y;
                }
                *(float2*)(S_v + (d << 6) + m2) = v;
            }
            __syncthreads();
            if (tid < 512) {   // PV: out[d][nn] = sum_m v[d][m] p[nn][m]
                int dg = tid >> 6;       // 0..7 warp-pair uniform
                int nn = tid & 63;
                const __half* pr = P + hl * PHEAD + nn * PSTR;
                float2 acc[4];
                acc[0] = acc[1] = acc[2] = acc[3] = make_float2(0.f, 0.f);
                #pragma unroll
                for (int j = 0; j < 8; j++) {
                    uint4 pv4 = *(const uint4*)(pr + (j << 3));
                    float2 p0 = __half22float2(*(__half2*)&pv4.x);
                    float2 p1 = __half22float2(*(__half2*)&pv4.y);
                    float2 p2 = __half22float2(*(__half2*)&pv4.z);
                    float2 p3 = __half22float2(*(__half2*)&pv4.w);
                    #pragma unroll
                    for (int dd = 0; dd < 4; dd++) {
                        const float4* vr = (const float4*)(S_v + (((dg << 2) + dd) << 6) + (j << 3));
                        float4 va = vr[0], vb2 = vr[1];
                        acc[dd] = ffma2(make_float2(va.x, va.y),  p0, acc[dd]);
                        acc[dd] = ffma2(make_float2(va.z, va.w),  p1, acc[dd]);
                        acc[dd] = ffma2(make_float2(vb2.x, vb2.y), p2, acc[dd]);
                        acc[dd] = ffma2(make_float2(vb2.z, vb2.w), p3, acc[dd]);
                    }
                }
                #pragma unroll
                for (int dd = 0; dd < 4; dd++)
                    S_ll[((ch0 + (dg << 2) + dd) << 6) + nn] = acc[dd].x + acc[dd].y;
            }
            __syncthreads();
        }
    }

    // ===== Phase C: relu + fp16 transpose + HMMA projection =====
    {
        // actT[n][c] fp16 (stride 264) = relu(S_ll[c][n])  (aliases P region)
        int nn = tid & 63;
        int c0 = (tid >> 6) << 4;         // 16-channel chunk
        __half2 hh[8];
        #pragma unroll
        for (int j = 0; j < 8; j++) {
            float f0 = fmaxf(S_ll[((c0 + 2*j    ) << 6) + nn], 0.f);
            float f1 = fmaxf(S_ll[((c0 + 2*j + 1) << 6) + nn], 0.f);
            hh[j] = __floats2half2_rn(f0, f1);
        }
        __syncthreads();                   // everyone done reading S_ll
        *(uint4*)(S_actT + nn * 264 + c0)     = *(uint4*)&hh[0];
        *(uint4*)(S_actT + nn * 264 + c0 + 8) = *(uint4*)&hh[4];
    }
    __syncthreads();
    {
        const int mt = wid >> 1;          // 16 m-tiles of 16 rows
        const int nh = wid & 1;           // n-half
        const int g  = lane >> 2;
        const int t  = lane & 3;
        float acc[4][4];
        #pragma unroll
        for (int i = 0; i < 4; i++)
            #pragma unroll
            for (int j = 0; j < 4; j++) acc[i][j] = 0.f;

        const uint4* afrag = (const uint4*)g_WpH + (mt << 9) + lane;
        const __half* bbase = S_actT + ((nh << 5) + g) * 264 + (t << 1);
        #pragma unroll 4
        for (int ks = 0; ks < 16; ks++) {
            uint4 a = afrag[ks << 5];
            const __half* bp = bbase + (ks << 4);
            #pragma unroll
            for (int ntl = 0; ntl < 4; ntl++) {
                uint32_t b0 = *(const uint32_t*)(bp + ntl * 8 * 264);
                uint32_t b1 = *(const uint32_t*)(bp + ntl * 8 * 264 + 8);
                hmma16816(acc[ntl], (const uint32_t*)&a, b0, b1);
            }
        }
        // epilogue: bias + store to S_ll
        int o0 = (mt << 4) + g;
        float pb0 = pjb[o0], pb1 = pjb[o0 + 8];
        int ncol = (nh << 5) + (t << 1);
        #pragma unroll
        for (int ntl = 0; ntl < 4; ntl++) {
            int nc = ncol + (ntl << 3);
            *(float2*)(S_ll + (o0 << 6) + nc) =
                make_float2(acc[ntl][0] + pb0, acc[ntl][1] + pb0);
            *(float2*)(S_ll + ((o0 + 8) << 6) + nc) =
                make_float2(acc[ntl][2] + pb1, acc[ntl][3] + pb1);
        }
    }
    __syncthreads();

    // ================= Phase D: inverse wavelet -> out =================
    for (int i = tid; i < 4096; i += NTH) S_iw[i] = iwtf[i];
    __syncthreads();
    {
        float* ob = out + (size_t)wb * (256u * 256u * 256u);
        #pragma unroll 4
        for (int rep = 0; rep < 8; rep++) {
            int u = tid + rep * NTH;
            int c = u >> 5;
            int i = (u >> 2) & 7;
            int k = u & 3;
            int o0 = (c << 6) + (i << 3) + (k << 1);
            const float* w = S_iw + (c << 4);
            float2 llv = *(const float2*)(S_ll + o0);
            float2 lh = __half22float2(*(const __half2*)(S_lh + o0));
            float2 hl = __half22float2(*(const __half2*)(S_hl + o0));
            float2 hh = __half22float2(*(const __half2*)(S_hh + o0));
            float4 r0, r1;
            r0.x = llv.x*w[0] + lh.x*w[4] + hl.x*w[8]  + hh.x*w[12];
            r0.y = llv.x*w[1] + lh.x*w[5] + hl.x*w[9]  + hh.x*w[13];
            r0.z = llv.y*w[0] + lh.y*w[4] + hl.y*w[8]  + hh.y*w[12];
            r0.w = llv.y*w[1] + lh.y*w[5] + hl.y*w[9]  + hh.y*w[13];
            r1.x = llv.x*w[2] + lh.x*w[6] + hl.x*w[10] + hh.x*w[14];
            r1.y = llv.x*w[3] + lh.x*w[7] + hl.x*w[11] + hh.x*w[15];
            r1.z = llv.y*w[2] + lh.y*w[6] + hl.y*w[10] + hh.y*w[14];
            r1.w = llv.y*w[3] + lh.y*w[7] + hl.y*w[11] + hh.y*w[15];
            int gy = (wy << 4) + (i << 1);
            int gx = (wx << 4) + (k << 2);
            float* q_ = ob + (((c << 8) + gy) << 8) + gx;
            *(float4*)q_ = r0;
            *(float4*)(q_ + 256) = r1;
        }
    }
}

extern "C" void kernel_launch(void* const* d_in, const int* in_sizes, int n_in,
                              void* d_out, int out_size) {
    const float* x    = (const float*)d_in[0];
    const float* wtf  = (const float*)d_in[1];
    const float* iwtf = (const float*)d_in[2];
    const float* dww  = (const float*)d_in[3];
    const float* dwb  = (const float*)d_in[4];
    const float* pjw  = (const float*)d_in[5];
    const float* pjb  = (const float*)d_in[6];
    const float* atb  = (const float*)d_in[7];
    const int*   bix  = (const int*)d_in[8];
    float* o = (float*)d_out;
    (void)in_sizes; (void)n_in; (void)out_size;
    prep_kernel<<<256, 256>>>(pjw);
    cudaFuncSetAttribute(wwa_kernel, cudaFuncAttributeMaxDynamicSharedMemorySize, SMEM_BYTES);
    wwa_kernel<<<512, NTH, SMEM_BYTES>>>(x, wtf, iwtf, dww, dwb, pjb, atb, bix, o);
}

// round 10
// speedup vs baseline: 4.7693x; 1.1668x over previous
#include <cuda_runtime.h>
#include <cuda_fp16.h>
#include <cstdint>

// WaveletWindowAttention fused kernel (R8 = R7 resubmit after infra failure):
// 1024 threads/CTA, 512 CTAs.
// vs R6: PV via HMMA with the head chain carried in C-fragments (v_next and
// actT[n][c] written straight from registers: transpose pass removed),
// Q stored transposed [cl][66] with conflict-free packed stores,
// ll stored fp16, proj output split over dead ll16/P regions.

#define NTH 1024
#define PSTR 72           // P row stride in halves
#define PHEAD 4608        // 64*72 halves per head
#define VSTR 72           // V16 row stride in halves
#define QT 66             // Q transposed row stride in halves

__device__ __half g_WpH[65536];   // proj weights fp16 in HMMA A-fragment order

__device__ __forceinline__ float2 ffma2(float2 a, float2 b, float2 c) {
    unsigned long long ua = *reinterpret_cast<unsigned long long*>(&a);
    unsigned long long ub = *reinterpret_cast<unsigned long long*>(&b);
    unsigned long long uc = *reinterpret_cast<unsigned long long*>(&c);
    unsigned long long ud;
    asm("fma.rn.f32x2 %0, %1, %2, %3;" : "=l"(ud) : "l"(ua), "l"(ub), "l"(uc));
    return *reinterpret_cast<float2*>(&ud);
}

// prep: pjw[o][c] fp32 -> g_WpH in [mt(16)][ks(16)][lane(32)][aidx(8)] order
__global__ void prep_kernel(const float* __restrict__ pjw) {
    int i = blockIdx.x * 256 + threadIdx.x;   // 65536
    int o = i >> 8, c = i & 255;
    int mt = o >> 4, m = o & 15;
    int ks = c >> 4, k = c & 15;
    int lane = ((m & 7) << 2) | ((k & 7) >> 1);
    int aidx = (k & 1) | (((m >> 3) & 1) << 1) | ((k >> 3) << 2);
    g_WpH[(((((mt << 4) + ks) << 5) + lane) << 3) + aidx] =
        __float2half(pjw[(o << 8) + c]);
}

__device__ __forceinline__ void hmma16816(float* c4, const uint32_t* a4,
                                          uint32_t b0, uint32_t b1) {
    asm volatile(
        "mma.sync.aligned.m16n8k16.row.col.f32.f16.f16.f32 "
        "{%0,%1,%2,%3}, {%4,%5,%6,%7}, {%8,%9}, {%0,%1,%2,%3};"
        : "+f"(c4[0]), "+f"(c4[1]), "+f"(c4[2]), "+f"(c4[3])
        : "r"(a4[0]), "r"(a4[1]), "r"(a4[2]), "r"(a4[3]), "r"(b0), "r"(b1));
}

// ---- shared memory layout (bytes) ----
// @0      ll16 f16 [256][64]  (32768)  | proj_out LO f32 [128][64] (phase C/D)
// @32768  S_lh f16 [256][64]  (32768)
// @65536  S_hl f16 [256][64]  (32768)
// @98304  S_hh f16 [256][64]  (32768)
// @131072 P f16 [4][64][72]   (36864)  | S_wt(A) | S_dw+S_db(B1a) | proj HI f32 [128][64]
// @167936 Q f16 [128][66]     (16896)
// @184832 actT f16 [64][264]  (33792)  | S_iw f32[4096] (phase D)
// @218624 V16 f16 [32][72]    (4608)
// @223232 S_bi u8 [4096]
// @227328 S_ab f32 [512]      -> end 229376
#define SMEM_BYTES 229376

__global__ void __launch_bounds__(NTH, 1)
wwa_kernel(const float* __restrict__ x,   const float* __restrict__ wtf,
           const float* __restrict__ iwtf,const float* __restrict__ dww,
           const float* __restrict__ dwb, const float* __restrict__ pjb,
           const float* __restrict__ atb, const int* __restrict__ bix,
           float* __restrict__ out)
{
    extern __shared__ unsigned char sm[];
    __half* LL16 = (__half*)sm;
    __half* S_lh = (__half*)(sm + 32768);
    __half* S_hl = (__half*)(sm + 65536);
    __half* S_hh = (__half*)(sm + 98304);
    __half* P    = (__half*)(sm + 131072);
    float*  S_wt = (float*)(sm + 131072);
    float*  S_dw = (float*)(sm + 131072);
    float*  S_db = (float*)(sm + 131072 + 12800);
    float*  PO_LO = (float*)sm;                 // proj rows 0..127
    float*  PO_HI = (float*)(sm + 131072);      // proj rows 128..255
    __half* Q    = (__half*)(sm + 167936);
    __half* actT = (__half*)(sm + 184832);
    float*  S_iw = (float*)(sm + 184832);
    __half* V16  = (__half*)(sm + 218624);
    unsigned char* S_bi = sm + 223232;
    float*  S_ab = (float*)(sm + 227328);

    const int tid  = threadIdx.x;
    const int wid  = tid >> 5;
    const int lane = tid & 31;
    const int widx = blockIdx.x;
    const int wb = widx >> 8;
    const int wy = (widx >> 4) & 15;
    const int wx = widx & 15;

    // ---- init tables ----
    for (int i = tid; i < 4096; i += NTH) S_wt[i] = wtf[i];
    for (int i = tid; i < 4096; i += NTH) S_bi[i] = (unsigned char)bix[i];
    for (int i = tid; i < 512;  i += NTH) S_ab[i] = atb[i];
    __syncthreads();

    // ================= Phase A: forward wavelet =================
    {
        const float* xb = x + (size_t)wb * (256u * 256u * 256u);
        #pragma unroll 4
        for (int rep = 0; rep < 8; rep++) {
            int u = tid + rep * NTH;        // (c, i, k)
            int c = u >> 5;
            int i = (u >> 2) & 7;
            int k = u & 3;
            int gy = (wy << 4) + (i << 1);
            int gx = (wx << 4) + (k << 2);
            const float* p = xb + (((c << 8) + gy) << 8) + gx;
            float4 a = *(const float4*)p;
            float4 b = *(const float4*)(p + 256);
            const float* w = S_wt + (c << 4);
            int o0 = (c << 6) + (i << 3) + (k << 1);
            float v0, v1;
            v0 = a.x*w[0] + a.y*w[1] + b.x*w[2] + b.y*w[3];
            v1 = a.z*w[0] + a.w*w[1] + b.z*w[2] + b.w*w[3];
            *(__half2*)(LL16 + o0) = __floats2half2_rn(v0, v1);
            v0 = a.x*w[4] + a.y*w[5] + b.x*w[6] + b.y*w[7];
            v1 = a.z*w[4] + a.w*w[5] + b.z*w[6] + b.w*w[7];
            *(__half2*)(S_lh + o0) = __floats2half2_rn(v0, v1);
            v0 = a.x*w[8] + a.y*w[9] + b.x*w[10] + b.y*w[11];
            v1 = a.z*w[8] + a.w*w[9] + b.z*w[10] + b.w*w[11];
            *(__half2*)(S_hl + o0) = __floats2half2_rn(v0, v1);
            v0 = a.x*w[12] + a.y*w[13] + b.x*w[14] + b.y*w[15];
            v1 = a.z*w[12] + a.w*w[13] + b.z*w[14] + b.w*w[15];
            *(__half2*)(S_hh + o0) = __floats2half2_rn(v0, v1);
        }
    }
    __syncthreads();

    // head-0 v init: V16[d][m] = LL16[d][m]
    {
        int d  = tid >> 5;
        int m2 = (tid & 31) << 1;
        *(__half2*)(V16 + d * VSTR + m2) = *(const __half2*)(LL16 + (d << 6) + m2);
    }

    // ================= Phase B: 2 batches of 4 heads =================
    for (int bb = 0; bb < 2; bb++) {
        // stage depthwise weights for this batch (aliases P; dead after B1a)
        __syncthreads();
        for (int i = tid; i < 3200; i += NTH) S_dw[i] = dww[bb * 3200 + i];
        if (tid < 128) S_db[tid] = dwb[(bb << 7) + tid];
        __syncthreads();

        // ---- B1a: q-conv for 128 channels -> Q[cl][n] fp16 (stride 66) ----
        #pragma unroll
        for (int rep = 0; rep < 4; rep++) {
            int e  = tid + rep * NTH;      // 4096 strips
            int cl = e >> 5;               // 0..127 warp-uniform
            int s  = e & 31;
            int py = s >> 2;
            int px0 = (s & 3) << 1;
            int base = px0 >> 1;           // 0..3
            float a0 = S_db[cl], a1 = a0;
            const float* wd = S_dw + cl * 25;
            const __half2* row = (const __half2*)(S_lh + (((bb << 7) + cl) << 6));
            #pragma unroll
            for (int uu = 0; uu < 5; uu++) {
                int yy = py + uu - 2;
                if ((unsigned)yy < 8u) {
                    const __half2* r = row + (yy << 2);
                    const float* w = wd + uu * 5;
                    if (base >= 1) {
                        float2 h = __half22float2(r[base - 1]);
                        a0 += h.x * w[0] + h.y * w[1];
                        a1 += h.y * w[0];
                    }
                    {
                        float2 h = __half22float2(r[base]);
                        a0 += h.x * w[2] + h.y * w[3];
                        a1 += h.x * w[1] + h.y * w[2];
                    }
                    if (base <= 2) {
                        float2 h = __half22float2(r[base + 1]);
                        a0 += h.x * w[4];
                        a1 += h.x * w[3] + h.y * w[4];
                    }
                }
            }
            int n = (py << 3) + px0;
            *(__half2*)(Q + cl * QT + n) = __floats2half2_rn(a0, a1);
        }
        __syncthreads();

        // ---- B1b: QK^T + bias + softmax for 4 heads -> P ----
        #pragma unroll
        for (int rep = 0; rep < 2; rep++) {
            int e  = tid + rep * NTH;      // 2048 slots (hl, n, m0)
            int m0 = (e & 7) << 3;
            int n  = (e >> 3) & 63;
            int hl = e >> 9;               // 0..3 warp-uniform
            const __half* qcol = Q + (hl << 5) * QT + n;
            float2 v2[4];
            v2[0] = v2[1] = v2[2] = v2[3] = make_float2(0.f, 0.f);
            const __half* kb = S_hl + (((bb << 7) + (hl << 5)) << 6) + m0;
            #pragma unroll 8
            for (int d = 0; d < 32; d++) {
                float qv = __half2float(qcol[d * QT]);
                float2 q2 = make_float2(qv, qv);
                uint4 kv = *(const uint4*)(kb + (d << 6));
                v2[0] = ffma2(q2, __half22float2(*(__half2*)&kv.x), v2[0]);
                v2[1] = ffma2(q2, __half22float2(*(__half2*)&kv.y), v2[1]);
                v2[2] = ffma2(q2, __half22float2(*(__half2*)&kv.z), v2[2]);
                v2[3] = ffma2(q2, __half22float2(*(__half2*)&kv.w), v2[3]);
            }
            float fv[8];
            uint2 bbv = *(const uint2*)(S_bi + (n << 6) + m0);
            const float* ab = S_ab + (((bb << 2) + hl) << 6);
            const float SC = 0.17677669529663687f;
            fv[0] = v2[0].x * SC + ab[(bbv.x)       & 255u];
            fv[1] = v2[0].y * SC + ab[(bbv.x >> 8)  & 255u];
            fv[2] = v2[1].x * SC + ab[(bbv.x >> 16) & 255u];
            fv[3] = v2[1].y * SC + ab[(bbv.x >> 24) & 255u];
            fv[4] = v2[2].x * SC + ab[(bbv.y)       & 255u];
            fv[5] = v2[2].y * SC + ab[(bbv.y >> 8)  & 255u];
            fv[6] = v2[3].x * SC + ab[(bbv.y >> 16) & 255u];
            fv[7] = v2[3].y * SC + ab[(bbv.y >> 24) & 255u];
            float mx = fv[0];
            #pragma unroll
            for (int j = 1; j < 8; j++) mx = fmaxf(mx, fv[j]);
            mx = fmaxf(mx, __shfl_xor_sync(0xffffffffu, mx, 1));
            mx = fmaxf(mx, __shfl_xor_sync(0xffffffffu, mx, 2));
            mx = fmaxf(mx, __shfl_xor_sync(0xffffffffu, mx, 4));
            float sum = 0.f;
            #pragma unroll
            for (int j = 0; j < 8; j++) { fv[j] = __expf(fv[j] - mx); sum += fv[j]; }
            sum += __shfl_xor_sync(0xffffffffu, sum, 1);
            sum += __shfl_xor_sync(0xffffffffu, sum, 2);
            sum += __shfl_xor_sync(0xffffffffu, sum, 4);
            float inv = 1.f / sum;
            uint4 pk;
            *(__half2*)&pk.x = __floats2half2_rn(fv[0]*inv, fv[1]*inv);
            *(__half2*)&pk.y = __floats2half2_rn(fv[2]*inv, fv[3]*inv);
            *(__half2*)&pk.z = __floats2half2_rn(fv[4]*inv, fv[5]*inv);
            *(__half2*)&pk.w = __floats2half2_rn(fv[6]*inv, fv[7]*inv);
            *(uint4*)(P + hl * PHEAD + n * PSTR + m0) = pk;
        }
        __syncthreads();

        // ---- B2: 4 chained heads, PV via HMMA ----
        for (int hl = 0; hl < 4; hl++) {
            const int hd  = (bb << 2) + hl;
            const int ch0 = hd << 5;
            float c[4] = {0.f, 0.f, 0.f, 0.f};
            const int mt = wid >> 3;          // valid for wid<16
            const int nt = wid & 7;
            const int g2 = lane >> 2;
            const int t2 = lane & 3;
            if (wid < 16) {
                const __half* ab2 = V16 + (mt * 16 + g2) * VSTR + (t2 << 1);
                const __half* bb2 = P + hl * PHEAD + ((nt << 3) + g2) * PSTR + (t2 << 1);
                #pragma unroll
                for (int ks = 0; ks < 4; ks++) {
                    uint32_t a4[4], b0, b1;
                    a4[0] = *(const uint32_t*)(ab2 + (ks << 4));
                    a4[1] = *(const uint32_t*)(ab2 + 8 * VSTR + (ks << 4));
                    a4[2] = *(const uint32_t*)(ab2 + (ks << 4) + 8);
                    a4[3] = *(const uint32_t*)(ab2 + 8 * VSTR + (ks << 4) + 8);
                    b0 = *(const uint32_t*)(bb2 + (ks << 4));
                    b1 = *(const uint32_t*)(bb2 + (ks << 4) + 8);
                    hmma16816(c, a4, b0, b1);
                }
            }
            __syncthreads();   // V16 reads complete
            if (wid < 16) {
                int d0 = mt * 16 + g2;
                int n0 = (nt << 3) + (t2 << 1);
                actT[n0 * 264 + ch0 + d0]           = __float2half(fmaxf(c[0], 0.f));
                actT[(n0 + 1) * 264 + ch0 + d0]     = __float2half(fmaxf(c[1], 0.f));
                actT[n0 * 264 + ch0 + d0 + 8]       = __float2half(fmaxf(c[2], 0.f));
                actT[(n0 + 1) * 264 + ch0 + d0 + 8] = __float2half(fmaxf(c[3], 0.f));
                if (hd < 7) {
                    float2 f0 = __half22float2(*(const __half2*)(LL16 + ((ch0 + 32 + d0) << 6) + n0));
                    float2 f1 = __half22float2(*(const __half2*)(LL16 + ((ch0 + 40 + d0) << 6) + n0));
                    *(__half2*)(V16 + d0 * VSTR + n0)       = __floats2half2_rn(c[0] + f0.x, c[1] + f0.y);
                    *(__half2*)(V16 + (d0 + 8) * VSTR + n0) = __floats2half2_rn(c[2] + f1.x, c[3] + f1.y);
                }
            }
            __syncthreads();
        }
    }

    // ===== Phase C: HMMA projection (actT already built by B2) =====
    {
        const int mt = wid >> 1;          // 16 m-tiles of 16 rows
        const int nh = wid & 1;           // n-half
        const int g  = lane >> 2;
        const int t  = lane & 3;
        float acc[4][4];
        #pragma unroll
        for (int i = 0; i < 4; i++)
            #pragma unroll
            for (int j = 0; j < 4; j++) acc[i][j] = 0.f;

        const uint4* afrag = (const uint4*)g_WpH + (mt << 9) + lane;
        const __half* bbase = actT + ((nh << 5) + g) * 264 + (t << 1);
        #pragma unroll 4
        for (int ks = 0; ks < 16; ks++) {
            uint4 a = afrag[ks << 5];
            const __half* bp = bbase + (ks << 4);
            #pragma unroll
            for (int ntl = 0; ntl < 4; ntl++) {
                uint32_t b0 = *(const uint32_t*)(bp + ntl * 8 * 264);
                uint32_t b1 = *(const uint32_t*)(bp + ntl * 8 * 264 + 8);
                hmma16816(acc[ntl], (const uint32_t*)&a, b0, b1);
            }
        }
        __syncthreads();   // all b-reads of actT done; P/ll16 regions now writable
        // epilogue: bias + store to split proj_out
        int o0 = (mt << 4) + g;
        float pb0 = pjb[o0], pb1 = pjb[o0 + 8];
        float* d0 = (o0 < 128) ? (PO_LO + (o0 << 6)) : (PO_HI + ((o0 - 128) << 6));
        float* d1 = (o0 < 128) ? (PO_LO + ((o0 + 8) << 6)) : (PO_HI + ((o0 - 120) << 6));
        int ncol = (nh << 5) + (t << 1);
        #pragma unroll
        for (int ntl = 0; ntl < 4; ntl++) {
            int nc = ncol + (ntl << 3);
            *(float2*)(d0 + nc) = make_float2(acc[ntl][0] + pb0, acc[ntl][1] + pb0);
            *(float2*)(d1 + nc) = make_float2(acc[ntl][2] + pb1, acc[ntl][3] + pb1);
        }
    }
    __syncthreads();

    // ================= Phase D: inverse wavelet -> out =================
    for (int i = tid; i < 4096; i += NTH) S_iw[i] = iwtf[i];
    __syncthreads();
    {
        float* ob = out + (size_t)wb * (256u * 256u * 256u);
        #pragma unroll 4
        for (int rep = 0; rep < 8; rep++) {
            int u = tid + rep * NTH;
            int c = u >> 5;
            int i = (u >> 2) & 7;
            int k = u & 3;
            int pix = (i << 3) + (k << 1);
            int o0 = (c << 6) + pix;
            const float* w = S_iw + (c << 4);
            const float* llrow = (c < 128) ? (PO_LO + (c << 6)) : (PO_HI + ((c - 128) << 6));
            float2 llv = *(const float2*)(llrow + pix);
            float2 lh = __half22float2(*(const __half2*)(S_lh + o0));
            float2 hl = __half22float2(*(const __half2*)(S_hl + o0));
            float2 hh = __half22float2(*(const __half2*)(S_hh + o0));
            float4 r0, r1;
            r0.x = llv.x*w[0] + lh.x*w[4] + hl.x*w[8]  + hh.x*w[12];
            r0.y = llv.x*w[1] + lh.x*w[5] + hl.x*w[9]  + hh.x*w[13];
            r0.z = llv.y*w[0] + lh.y*w[4] + hl.y*w[8]  + hh.y*w[12];
            r0.w = llv.y*w[1] + lh.y*w[5] + hl.y*w[9]  + hh.y*w[13];
            r1.x = llv.x*w[2] + lh.x*w[6] + hl.x*w[10] + hh.x*w[14];
            r1.y = llv.x*w[3] + lh.x*w[7] + hl.x*w[11] + hh.x*w[15];
            r1.z = llv.y*w[2] + lh.y*w[6] + hl.y*w[10] + hh.y*w[14];
            r1.w = llv.y*w[3] + lh.y*w[7] + hl.y*w[11] + hh.y*w[15];
            int gy = (wy << 4) + (i << 1);
            int gx = (wx << 4) + (k << 2);
            float* q_ = ob + (((c << 8) + gy) << 8) + gx;
            *(float4*)q_ = r0;
            *(float4*)(q_ + 256) = r1;
        }
    }
}

extern "C" void kernel_launch(void* const* d_in, const int* in_sizes, int n_in,
                              void* d_out, int out_size) {
    const float* x    = (const float*)d_in[0];
    const float* wtf  = (const float*)d_in[1];
    const float* iwtf = (const float*)d_in[2];
    const float* dww  = (const float*)d_in[3];
    const float* dwb  = (const float*)d_in[4];
    const float* pjw  = (const float*)d_in[5];
    const float* pjb  = (const float*)d_in[6];
    const float* atb  = (const float*)d_in[7];
    const int*   bix  = (const int*)d_in[8];
    float* o = (float*)d_out;
    (void)in_sizes; (void)n_in; (void)out_size;
    prep_kernel<<<256, 256>>>(pjw);
    cudaFuncSetAttribute(wwa_kernel, cudaFuncAttributeMaxDynamicSharedMemorySize, SMEM_BYTES);
    wwa_kernel<<<512, NTH, SMEM_BYTES>>>(x, wtf, iwtf, dww, dwb, pjb, atb, bix, o);
}

// round 11
// speedup vs baseline: 5.9401x; 1.2455x over previous
#include <cuda_runtime.h>
#include <cuda_fp16.h>
#include <cstdint>

// WaveletWindowAttention fused kernel (R9): 1024 threads/CTA, 512 CTAs.
// vs R8: QK^T via HMMA (hl stored transposed hlT[m][c]; Q stored [n][cl]),
// softmax fully in registers via quad shuffles (no logit smem round-trip),
// depthwise conv weights via warp-uniform __ldg (staging pass + barriers gone).

#define NTH 1024
#define PSTR 72           // P row stride in halves
#define PHEAD 4608        // 64*72 halves per head
#define VSTR 72           // V16 row stride in halves
#define QS 134            // Q [n][cl] row stride in halves
#define HTS 258           // hlT [m][c] row stride in halves

__device__ __half g_WpH[65536];   // proj weights fp16 in HMMA A-fragment order

// prep: pjw[o][c] fp32 -> g_WpH in [mt(16)][ks(16)][lane(32)][aidx(8)] order
__global__ void prep_kernel(const float* __restrict__ pjw) {
    int i = blockIdx.x * 256 + threadIdx.x;   // 65536
    int o = i >> 8, c = i & 255;
    int mt = o >> 4, m = o & 15;
    int ks = c >> 4, k = c & 15;
    int lane = ((m & 7) << 2) | ((k & 7) >> 1);
    int aidx = (k & 1) | (((m >> 3) & 1) << 1) | ((k >> 3) << 2);
    g_WpH[(((((mt << 4) + ks) << 5) + lane) << 3) + aidx] =
        __float2half(pjw[(o << 8) + c]);
}

__device__ __forceinline__ void hmma16816(float* c4, const uint32_t* a4,
                                          uint32_t b0, uint32_t b1) {
    asm volatile(
        "mma.sync.aligned.m16n8k16.row.col.f32.f16.f16.f32 "
        "{%0,%1,%2,%3}, {%4,%5,%6,%7}, {%8,%9}, {%0,%1,%2,%3};"
        : "+f"(c4[0]), "+f"(c4[1]), "+f"(c4[2]), "+f"(c4[3])
        : "r"(a4[0]), "r"(a4[1]), "r"(a4[2]), "r"(a4[3]), "r"(b0), "r"(b1));
}

// ---- shared memory layout (bytes) ----
// @0      LL16 f16 [256][64] (32768) | PO_LO f32 [128][64] (phase C/D)
// @32768  S_lh f16 [256][64] (32768)
// @65536  hlT  f16 [64][258] (33024)
// @98560  S_hh f16 [256][64] (32768)
// @131328 P f16 [4][64][72] (36864) | S_wt(A) | PO_HI f32 [128][64]
// @168192 Q f16 [64][134]   (17152)
// @185344 actT f16 [64][264] (33792) | S_iw f32[4096] (phase D)
// @219136 V16 f16 [32][72]  (4608)
// @223744 S_bi u8 [4096]
// @227840 S_ab f32 [512]    -> end 229888
#define SMEM_BYTES 229888

__global__ void __launch_bounds__(NTH, 1)
wwa_kernel(const float* __restrict__ x,   const float* __restrict__ wtf,
           const float* __restrict__ iwtf,const float* __restrict__ dww,
           const float* __restrict__ dwb, const float* __restrict__ pjb,
           const float* __restrict__ atb, const int* __restrict__ bix,
           float* __restrict__ out)
{
    extern __shared__ unsigned char sm[];
    __half* LL16 = (__half*)sm;
    __half* S_lh = (__half*)(sm + 32768);
    __half* hlT  = (__half*)(sm + 65536);
    __half* S_hh = (__half*)(sm + 98560);
    __half* P    = (__half*)(sm + 131328);
    float*  S_wt = (float*)(sm + 131328);
    float*  PO_LO = (float*)sm;                 // proj rows 0..127
    float*  PO_HI = (float*)(sm + 131328);      // proj rows 128..255
    __half* Q    = (__half*)(sm + 168192);
    __half* actT = (__half*)(sm + 185344);
    float*  S_iw = (float*)(sm + 185344);
    __half* V16  = (__half*)(sm + 219136);
    unsigned char* S_bi = sm + 223744;
    float*  S_ab = (float*)(sm + 227840);

    const int tid  = threadIdx.x;
    const int wid  = tid >> 5;
    const int lane = tid & 31;
    const int widx = blockIdx.x;
    const int wb = widx >> 8;
    const int wy = (widx >> 4) & 15;
    const int wx = widx & 15;

    // ---- init tables ----
    for (int i = tid; i < 4096; i += NTH) S_wt[i] = wtf[i];
    for (int i = tid; i < 4096; i += NTH) S_bi[i] = (unsigned char)bix[i];
    for (int i = tid; i < 512;  i += NTH) S_ab[i] = atb[i];
    __syncthreads();

    // ================= Phase A: forward wavelet =================
    {
        const float* xb = x + (size_t)wb * (256u * 256u * 256u);
        #pragma unroll 4
        for (int rep = 0; rep < 8; rep++) {
            int u = tid + rep * NTH;        // (c, i, k)
            int c = u >> 5;
            int i = (u >> 2) & 7;
            int k = u & 3;
            int gy = (wy << 4) + (i << 1);
            int gx = (wx << 4) + (k << 2);
            const float* p = xb + (((c << 8) + gy) << 8) + gx;
            float4 a = *(const float4*)p;
            float4 b = *(const float4*)(p + 256);
            const float* w = S_wt + (c << 4);
            int pix = (i << 3) + (k << 1);
            int o0 = (c << 6) + pix;
            float v0, v1;
            v0 = a.x*w[0] + a.y*w[1] + b.x*w[2] + b.y*w[3];
            v1 = a.z*w[0] + a.w*w[1] + b.z*w[2] + b.w*w[3];
            *(__half2*)(LL16 + o0) = __floats2half2_rn(v0, v1);
            v0 = a.x*w[4] + a.y*w[5] + b.x*w[6] + b.y*w[7];
            v1 = a.z*w[4] + a.w*w[5] + b.z*w[6] + b.w*w[7];
            *(__half2*)(S_lh + o0) = __floats2half2_rn(v0, v1);
            v0 = a.x*w[8] + a.y*w[9] + b.x*w[10] + b.y*w[11];
            v1 = a.z*w[8] + a.w*w[9] + b.z*w[10] + b.w*w[11];
            hlT[pix * HTS + c]       = __float2half(v0);
            hlT[(pix + 1) * HTS + c] = __float2half(v1);
            v0 = a.x*w[12] + a.y*w[13] + b.x*w[14] + b.y*w[15];
            v1 = a.z*w[12] + a.w*w[13] + b.z*w[14] + b.w*w[15];
            *(__half2*)(S_hh + o0) = __floats2half2_rn(v0, v1);
        }
    }
    __syncthreads();

    // head-0 v init: V16[d][m] = LL16[d][m]
    {
        int d  = tid >> 5;
        int m2 = (tid & 31) << 1;
        *(__half2*)(V16 + d * VSTR + m2) = *(const __half2*)(LL16 + (d << 6) + m2);
    }

    // ================= Phase B: 2 batches of 4 heads =================
    for (int bb = 0; bb < 2; bb++) {
        // ---- B1a: q-conv for 128 channels -> Q[n][cl] fp16 (stride 134) ----
        #pragma unroll
        for (int rep = 0; rep < 4; rep++) {
            int e  = tid + rep * NTH;      // 4096 strips
            int cl = e >> 5;               // 0..127 warp-uniform
            int s  = e & 31;
            int py = s >> 2;
            int px0 = (s & 3) << 1;
            int base = px0 >> 1;           // 0..3
            const float* wd = dww + bb * 3200 + cl * 25;
            float a0 = __ldg(dwb + (bb << 7) + cl), a1 = a0;
            const __half2* row = (const __half2*)(S_lh + (((bb << 7) + cl) << 6));
            #pragma unroll
            for (int uu = 0; uu < 5; uu++) {
                int yy = py + uu - 2;
                if ((unsigned)yy < 8u) {
                    const __half2* r = row + (yy << 2);
                    const float* w = wd + uu * 5;
                    if (base >= 1) {
                        float2 h = __half22float2(r[base - 1]);
                        a0 += h.x * w[0] + h.y * w[1];
                        a1 += h.y * w[0];
                    }
                    {
                        float2 h = __half22float2(r[base]);
                        a0 += h.x * w[2] + h.y * w[3];
                        a1 += h.x * w[1] + h.y * w[2];
                    }
                    if (base <= 2) {
                        float2 h = __half22float2(r[base + 1]);
                        a0 += h.x * w[4];
                        a1 += h.x * w[3] + h.y * w[4];
                    }
                }
            }
            int n = (py << 3) + px0;
            Q[n * QS + cl]       = __float2half(a0);
            Q[(n + 1) * QS + cl] = __float2half(a1);
        }
        __syncthreads();

        // ---- B1b: QK^T via HMMA + register softmax -> P (16 warps) ----
        if (wid < 16) {
            const int hl = wid >> 2;       // head-in-batch
            const int mt = wid & 3;        // 16-row n tile
            const int g  = lane >> 2;
            const int t  = lane & 3;
            const int chb = hl << 5;
            const __half* qb = Q + (mt * 16 + g) * QS + chb + (t << 1);
            uint32_t A0[4], A1[4];
            A0[0] = *(const uint32_t*)(qb);
            A0[1] = *(const uint32_t*)(qb + 8 * QS);
            A0[2] = *(const uint32_t*)(qb + 8);
            A0[3] = *(const uint32_t*)(qb + 8 * QS + 8);
            A1[0] = *(const uint32_t*)(qb + 16);
            A1[1] = *(const uint32_t*)(qb + 8 * QS + 16);
            A1[2] = *(const uint32_t*)(qb + 24);
            A1[3] = *(const uint32_t*)(qb + 8 * QS + 24);
            float fv0[16], fv1[16];
            const __half* bt = hlT + (bb << 7) + chb + (t << 1);
            #pragma unroll
            for (int nt = 0; nt < 8; nt++) {
                float c[4] = {0.f, 0.f, 0.f, 0.f};
                const __half* bp = bt + ((nt << 3) + g) * HTS;
                uint32_t b0 = *(const uint32_t*)(bp);
                uint32_t b1 = *(const uint32_t*)(bp + 8);
                hmma16816(c, A0, b0, b1);
                b0 = *(const uint32_t*)(bp + 16);
                b1 = *(const uint32_t*)(bp + 24);
                hmma16816(c, A1, b0, b1);
                fv0[nt*2] = c[0]; fv0[nt*2+1] = c[1];
                fv1[nt*2] = c[2]; fv1[nt*2+1] = c[3];
            }
            const float* ab = S_ab + (((bb << 2) + hl) << 6);
            const float SC = 0.17677669529663687f;
            #pragma unroll
            for (int r = 0; r < 2; r++) {
                float* fv = r ? fv1 : fv0;
                int n = mt * 16 + g + (r << 3);
                const unsigned char* bi = S_bi + (n << 6) + (t << 1);
                #pragma unroll
                for (int nt = 0; nt < 8; nt++) {
                    uint16_t b2 = *(const uint16_t*)(bi + (nt << 3));
                    fv[nt*2]   = fv[nt*2]   * SC + ab[b2 & 255u];
                    fv[nt*2+1] = fv[nt*2+1] * SC + ab[b2 >> 8];
                }
                float mx = fv[0];
                #pragma unroll
                for (int j = 1; j < 16; j++) mx = fmaxf(mx, fv[j]);
                mx = fmaxf(mx, __shfl_xor_sync(0xffffffffu, mx, 1));
                mx = fmaxf(mx, __shfl_xor_sync(0xffffffffu, mx, 2));
                float sum = 0.f;
                #pragma unroll
                for (int j = 0; j < 16; j++) { fv[j] = __expf(fv[j] - mx); sum += fv[j]; }
                sum += __shfl_xor_sync(0xffffffffu, sum, 1);
                sum += __shfl_xor_sync(0xffffffffu, sum, 2);
                float inv = 1.f / sum;
                __half* pr = P + hl * PHEAD + n * PSTR + (t << 1);
                #pragma unroll
                for (int nt = 0; nt < 8; nt++)
                    *(__half2*)(pr + (nt << 3)) =
                        __floats2half2_rn(fv[nt*2] * inv, fv[nt*2+1] * inv);
            }
        }
        __syncthreads();

        // ---- B2: 4 chained heads, PV via HMMA ----
        for (int hl = 0; hl < 4; hl++) {
            const int hd  = (bb << 2) + hl;
            const int ch0 = hd << 5;
            float c[4] = {0.f, 0.f, 0.f, 0.f};
            const int mt = wid >> 3;          // valid for wid<16
            const int nt = wid & 7;
            const int g2 = lane >> 2;
            const int t2 = lane & 3;
            if (wid < 16) {
                const __half* ab2 = V16 + (mt * 16 + g2) * VSTR + (t2 << 1);
                const __half* bb2 = P + hl * PHEAD + ((nt << 3) + g2) * PSTR + (t2 << 1);
                #pragma unroll
                for (int ks = 0; ks < 4; ks++) {
                    uint32_t a4[4], b0, b1;
                    a4[0] = *(const uint32_t*)(ab2 + (ks << 4));
                    a4[1] = *(const uint32_t*)(ab2 + 8 * VSTR + (ks << 4));
                    a4[2] = *(const uint32_t*)(ab2 + (ks << 4) + 8);
                    a4[3] = *(const uint32_t*)(ab2 + 8 * VSTR + (ks << 4) + 8);
                    b0 = *(const uint32_t*)(bb2 + (ks << 4));
                    b1 = *(const uint32_t*)(bb2 + (ks << 4) + 8);
                    hmma16816(c, a4, b0, b1);
                }
            }
            __syncthreads();   // V16 reads complete
            if (wid < 16) {
                int d0 = mt * 16 + g2;
                int n0 = (nt << 3) + (t2 << 1);
                actT[n0 * 264 + ch0 + d0]           = __float2half(fmaxf(c[0], 0.f));
                actT[(n0 + 1) * 264 + ch0 + d0]     = __float2half(fmaxf(c[1], 0.f));
                actT[n0 * 264 + ch0 + d0 + 8]       = __float2half(fmaxf(c[2], 0.f));
                actT[(n0 + 1) * 264 + ch0 + d0 + 8] = __float2half(fmaxf(c[3], 0.f));
                if (hd < 7) {
                    float2 f0 = __half22float2(*(const __half2*)(LL16 + ((ch0 + 32 + d0) << 6) + n0));
                    float2 f1 = __half22float2(*(const __half2*)(LL16 + ((ch0 + 40 + d0) << 6) + n0));
                    *(__half2*)(V16 + d0 * VSTR + n0)       = __floats2half2_rn(c[0] + f0.x, c[1] + f0.y);
                    *(__half2*)(V16 + (d0 + 8) * VSTR + n0) = __floats2half2_rn(c[2] + f1.x, c[3] + f1.y);
                }
            }
            __syncthreads();
        }
    }

    // ===== Phase C: HMMA projection (actT already built by B2) =====
    {
        const int mt = wid >> 1;          // 16 m-tiles of 16 rows
        const int nh = wid & 1;           // n-half
        const int g  = lane >> 2;
        const int t  = lane & 3;
        float acc[4][4];
        #pragma unroll
        for (int i = 0; i < 4; i++)
            #pragma unroll
            for (int j = 0; j < 4; j++) acc[i][j] = 0.f;

        const uint4* afrag = (const uint4*)g_WpH + (mt << 9) + lane;
        const __half* bbase = actT + ((nh << 5) + g) * 264 + (t << 1);
        #pragma unroll 4
        for (int ks = 0; ks < 16; ks++) {
            uint4 a = afrag[ks << 5];
            const __half* bp = bbase + (ks << 4);
            #pragma unroll
            for (int ntl = 0; ntl < 4; ntl++) {
                uint32_t b0 = *(const uint32_t*)(bp + ntl * 8 * 264);
                uint32_t b1 = *(const uint32_t*)(bp + ntl * 8 * 264 + 8);
                hmma16816(acc[ntl], (const uint32_t*)&a, b0, b1);
            }
        }
        __syncthreads();   // all b-reads of actT done; P/LL16 regions now writable
        // epilogue: bias + store to split proj_out
        int o0 = (mt << 4) + g;
        float pb0 = pjb[o0], pb1 = pjb[o0 + 8];
        float* d0 = (o0 < 128) ? (PO_LO + (o0 << 6)) : (PO_HI + ((o0 - 128) << 6));
        float* d1 = (o0 < 128) ? (PO_LO + ((o0 + 8) << 6)) : (PO_HI + ((o0 - 120) << 6));
        int ncol = (nh << 5) + (t << 1);
        #pragma unroll
        for (int ntl = 0; ntl < 4; ntl++) {
            int nc = ncol + (ntl << 3);
            *(float2*)(d0 + nc) = make_float2(acc[ntl][0] + pb0, acc[ntl][1] + pb0);
            *(float2*)(d1 + nc) = make_float2(acc[ntl][2] + pb1, acc[ntl][3] + pb1);
        }
    }
    __syncthreads();

    // ================= Phase D: inverse wavelet -> out =================
    for (int i = tid; i < 4096; i += NTH) S_iw[i] = iwtf[i];
    __syncthreads();
    {
        float* ob = out + (size_t)wb * (256u * 256u * 256u);
        #pragma unroll 4
        for (int rep = 0; rep < 8; rep++) {
            int u = tid + rep * NTH;
            int c = u >> 5;
            int i = (u >> 2) & 7;
            int k = u & 3;
            int pix = (i << 3) + (k << 1);
            int o0 = (c << 6) + pix;
            const float* w = S_iw + (c << 4);
            const float* llrow = (c < 128) ? (PO_LO + (c << 6)) : (PO_HI + ((c - 128) << 6));
            float2 llv = *(const float2*)(llrow + pix);
            float2 lh = __half22float2(*(const __half2*)(S_lh + o0));
            float2 hl;
            hl.x = __half2float(hlT[pix * HTS + c]);
            hl.y = __half2float(hlT[(pix + 1) * HTS + c]);
            float2 hh = __half22float2(*(const __half2*)(S_hh + o0));
            float4 r0, r1;
            r0.x = llv.x*w[0] + lh.x*w[4] + hl.x*w[8]  + hh.x*w[12];
            r0.y = llv.x*w[1] + lh.x*w[5] + hl.x*w[9]  + hh.x*w[13];
            r0.z = llv.y*w[0] + lh.y*w[4] + hl.y*w[8]  + hh.y*w[12];
            r0.w = llv.y*w[1] + lh.y*w[5] + hl.y*w[9]  + hh.y*w[13];
            r1.x = llv.x*w[2] + lh.x*w[6] + hl.x*w[10] + hh.x*w[14];
            r1.y = llv.x*w[3] + lh.x*w[7] + hl.x*w[11] + hh.x*w[15];
            r1.z = llv.y*w[2] + lh.y*w[6] + hl.y*w[10] + hh.y*w[14];
            r1.w = llv.y*w[3] + lh.y*w[7] + hl.y*w[11] + hh.y*w[15];
            int gy = (wy << 4) + (i << 1);
            int gx = (wx << 4) + (k << 2);
            float* q_ = ob + (((c << 8) + gy) << 8) + gx;
            *(float4*)q_ = r0;
            *(float4*)(q_ + 256) = r1;
        }
    }
}

extern "C" void kernel_launch(void* const* d_in, const int* in_sizes, int n_in,
                              void* d_out, int out_size) {
    const float* x    = (const float*)d_in[0];
    const float* wtf  = (const float*)d_in[1];
    const float* iwtf = (const float*)d_in[2];
    const float* dww  = (const float*)d_in[3];
    const float* dwb  = (const float*)d_in[4];
    const float* pjw  = (const float*)d_in[5];
    const float* pjb  = (const float*)d_in[6];
    const float* atb  = (const float*)d_in[7];
    const int*   bix  = (const int*)d_in[8];
    float* o = (float*)d_out;
    (void)in_sizes; (void)n_in; (void)out_size;
    prep_kernel<<<256, 256>>>(pjw);
    cudaFuncSetAttribute(wwa_kernel, cudaFuncAttributeMaxDynamicSharedMemorySize, SMEM_BYTES);
    wwa_kernel<<<512, NTH, SMEM_BYTES>>>(x, wtf, iwtf, dww, dwb, pjb, atb, bix, o);
}

// round 12
// speedup vs baseline: 6.1638x; 1.0377x over previous
#include <cuda_runtime.h>
#include <cuda_fp16.h>
#include <cstdint>

// WaveletWindowAttention fused kernel (R11): 1024 threads/CTA, 512 CTAs.
// vs R10: warp specialization — while warps 0-15 run B1b+B2 of batch b
// (named barriers bar.sync 3,512), warps 16-31 run B1a q-conv of batch b+1
// (batch 0) or prefetch iwtf into the dead Q region (batch 1).
// Q WAR hazard closed by bar.sync 4,1024 after B1b's up-front Q reads.

#define NTH 1024
#define PSTR 72           // P row stride in halves
#define PHEAD 4608        // 64*72 halves per head
#define VSTR 72           // V16 row stride in halves
#define QS 134            // Q [n][cl] row stride in halves
#define HTS 258           // hlT [m][c] row stride in halves

__device__ __half g_WpH[65536];   // proj weights fp16 in HMMA A-fragment order

// prep: pjw[o][c] fp32 -> g_WpH in [mt(16)][ks(16)][lane(32)][aidx(8)] order
__global__ void prep_kernel(const float* __restrict__ pjw) {
    int i = blockIdx.x * 256 + threadIdx.x;   // 65536
    int o = i >> 8, c = i & 255;
    int mt = o >> 4, m = o & 15;
    int ks = c >> 4, k = c & 15;
    int lane = ((m & 7) << 2) | ((k & 7) >> 1);
    int aidx = (k & 1) | (((m >> 3) & 1) << 1) | ((k >> 3) << 2);
    g_WpH[(((((mt << 4) + ks) << 5) + lane) << 3) + aidx] =
        __float2half(pjw[(o << 8) + c]);
}

__device__ __forceinline__ void hmma16816(float* c4, const uint32_t* a4,
                                          uint32_t b0, uint32_t b1) {
    asm volatile(
        "mma.sync.aligned.m16n8k16.row.col.f32.f16.f16.f32 "
        "{%0,%1,%2,%3}, {%4,%5,%6,%7}, {%8,%9}, {%0,%1,%2,%3};"
        : "+f"(c4[0]), "+f"(c4[1]), "+f"(c4[2]), "+f"(c4[3])
        : "r"(a4[0]), "r"(a4[1]), "r"(a4[2]), "r"(a4[3]), "r"(b0), "r"(b1));
}

__device__ __forceinline__ void barn(int id, int cnt) {
    asm volatile("bar.sync %0, %1;" :: "r"(id), "r"(cnt) : "memory");
}

// ---- shared memory layout (bytes) ----
// @0      LL16 f16 [256][64] (32768) | PO_LO f32 [128][64] (phase C/D)
// @32768  S_lh f16 [256][64] (32768)
// @65536  hlT  f16 [64][258] (33024)
// @98560  S_hh f16 [256][64] (32768)
// @131328 P f16 [4][64][72] (36864) | S_wt(A) | PO_HI f32 [128][64]
// @168192 Q f16 [64][134]   (17152) | IW f32[4096] (loaded during B2(b1))
// @185344 actT f16 [64][264] (33792)
// @219136 V16 f16 [32][72]  (4608)
// @223744 S_bi u8 [4096]
// @227840 S_ab f32 [512]    -> end 229888
#define SMEM_BYTES 229888

__global__ void __launch_bounds__(NTH, 1)
wwa_kernel(const float* __restrict__ x,   const float* __restrict__ wtf,
           const float* __restrict__ iwtf,const float* __restrict__ dww,
           const float* __restrict__ dwb, const float* __restrict__ pjb,
           const float* __restrict__ atb, const int* __restrict__ bix,
           float* __restrict__ out)
{
    extern __shared__ unsigned char sm[];
    __half* LL16 = (__half*)sm;
    __half* S_lh = (__half*)(sm + 32768);
    __half* hlT  = (__half*)(sm + 65536);
    __half* S_hh = (__half*)(sm + 98560);
    __half* P    = (__half*)(sm + 131328);
    float*  S_wt = (float*)(sm + 131328);
    float*  PO_LO = (float*)sm;                 // proj rows 0..127
    float*  PO_HI = (float*)(sm + 131328);      // proj rows 128..255
    __half* Q    = (__half*)(sm + 168192);
    float*  IW   = (float*)(sm + 168192);       // iwtf, loaded during B2(b1)
    __half* actT = (__half*)(sm + 185344);
    __half* V16  = (__half*)(sm + 219136);
    unsigned char* S_bi = sm + 223744;
    float*  S_ab = (float*)(sm + 227840);

    const int tid  = threadIdx.x;
    const int wid  = tid >> 5;
    const int lane = tid & 31;
    const int widx = blockIdx.x;
    const int wb = widx >> 8;
    const int wy = (widx >> 4) & 15;
    const int wx = widx & 15;

    // ---- init tables ----
    for (int i = tid; i < 4096; i += NTH) S_wt[i] = wtf[i];
    for (int i = tid; i < 4096; i += NTH) S_bi[i] = (unsigned char)bix[i];
    for (int i = tid; i < 512;  i += NTH) S_ab[i] = atb[i];
    __syncthreads();

    // ================= Phase A: forward wavelet =================
    {
        const float* xb = x + (size_t)wb * (256u * 256u * 256u);
        #pragma unroll 4
        for (int rep = 0; rep < 8; rep++) {
            int u = tid + rep * NTH;        // (c, i, k)
            int c = u >> 5;
            int i = (u >> 2) & 7;
            int k = u & 3;
            int gy = (wy << 4) + (i << 1);
            int gx = (wx << 4) + (k << 2);
            const float* p = xb + (((c << 8) + gy) << 8) + gx;
            float4 a = *(const float4*)p;
            float4 b = *(const float4*)(p + 256);
            const float* w = S_wt + (c << 4);
            int pix = (i << 3) + (k << 1);
            int o0 = (c << 6) + pix;
            float v0, v1;
            v0 = a.x*w[0] + a.y*w[1] + b.x*w[2] + b.y*w[3];
            v1 = a.z*w[0] + a.w*w[1] + b.z*w[2] + b.w*w[3];
            *(__half2*)(LL16 + o0) = __floats2half2_rn(v0, v1);
            v0 = a.x*w[4] + a.y*w[5] + b.x*w[6] + b.y*w[7];
            v1 = a.z*w[4] + a.w*w[5] + b.z*w[6] + b.w*w[7];
            *(__half2*)(S_lh + o0) = __floats2half2_rn(v0, v1);
            v0 = a.x*w[8] + a.y*w[9] + b.x*w[10] + b.y*w[11];
            v1 = a.z*w[8] + a.w*w[9] + b.z*w[10] + b.w*w[11];
            hlT[pix * HTS + c]       = __float2half(v0);
            hlT[(pix + 1) * HTS + c] = __float2half(v1);
            v0 = a.x*w[12] + a.y*w[13] + b.x*w[14] + b.y*w[15];
            v1 = a.z*w[12] + a.w*w[13] + b.z*w[14] + b.w*w[15];
            *(__half2*)(S_hh + o0) = __floats2half2_rn(v0, v1);
        }
    }

    // head-0 v init: V16[d][m] = LL16[d][m]  (no barrier needed before: same
    // threads wrote LL16?? -> no, LL16 rows by other warps; need sync first)
    __syncthreads();
    {
        int d  = tid >> 5;
        int m2 = (tid & 31) << 1;
        *(__half2*)(V16 + d * VSTR + m2) = *(const __half2*)(LL16 + (d << 6) + m2);
    }

    // ---- B1a(batch0): q-conv channels 0..127, all 32 warps ----
    #pragma unroll
    for (int rep = 0; rep < 4; rep++) {
        int e  = tid + rep * NTH;      // 4096 strips
        int cl = e >> 5;               // warp-uniform
        int s  = e & 31;
        int py = s >> 2;
        int px0 = (s & 3) << 1;
        int base = px0 >> 1;
        const float* wd = dww + cl * 25;
        float a0 = __ldg(dwb + cl), a1 = a0;
        const __half2* row = (const __half2*)(S_lh + (cl << 6));
        #pragma unroll
        for (int uu = 0; uu < 5; uu++) {
            int yy = py + uu - 2;
            if ((unsigned)yy < 8u) {
                const __half2* r = row + (yy << 2);
                const float* w = wd + uu * 5;
                if (base >= 1) {
                    float2 h = __half22float2(r[base - 1]);
                    a0 += h.x * w[0] + h.y * w[1];
                    a1 += h.y * w[0];
                }
                {
                    float2 h = __half22float2(r[base]);
                    a0 += h.x * w[2] + h.y * w[3];
                    a1 += h.x * w[1] + h.y * w[2];
                }
                if (base <= 2) {
                    float2 h = __half22float2(r[base + 1]);
                    a0 += h.x * w[4];
                    a1 += h.x * w[3] + h.y * w[4];
                }
            }
        }
        int n = (py << 3) + px0;
        Q[n * QS + cl]       = __float2half(a0);
        Q[(n + 1) * QS + cl] = __float2half(a1);
    }
    __syncthreads();

    // ================= Phase B: 2 batches, warp-specialized =================
    for (int bb = 0; bb < 2; bb++) {
        if (wid < 16) {
            // ---- B1b(bb): QK^T via HMMA + register softmax -> P ----
            const int hl = wid >> 2;
            const int mt = wid & 3;
            const int g  = lane >> 2;
            const int t  = lane & 3;
            const int chb = hl << 5;
            const __half* qb = Q + (mt * 16 + g) * QS + chb + (t << 1);
            uint32_t A0[4], A1[4];
            A0[0] = *(const uint32_t*)(qb);
            A0[1] = *(const uint32_t*)(qb + 8 * QS);
            A0[2] = *(const uint32_t*)(qb + 8);
            A0[3] = *(const uint32_t*)(qb + 8 * QS + 8);
            A1[0] = *(const uint32_t*)(qb + 16);
            A1[1] = *(const uint32_t*)(qb + 8 * QS + 16);
            A1[2] = *(const uint32_t*)(qb + 24);
            A1[3] = *(const uint32_t*)(qb + 8 * QS + 24);
            barn(4, 1024);                 // Q reads done -> other half may reuse Q
            float fv0[16], fv1[16];
            const __half* bt = hlT + (bb << 7) + chb + (t << 1);
            #pragma unroll
            for (int nt = 0; nt < 8; nt++) {
                float c[4] = {0.f, 0.f, 0.f, 0.f};
                const __half* bp = bt + ((nt << 3) + g) * HTS;
                uint32_t b0 = *(const uint32_t*)(bp);
                uint32_t b1 = *(const uint32_t*)(bp + 8);
                hmma16816(c, A0, b0, b1);
                b0 = *(const uint32_t*)(bp + 16);
                b1 = *(const uint32_t*)(bp + 24);
                hmma16816(c, A1, b0, b1);
                fv0[nt*2] = c[0]; fv0[nt*2+1] = c[1];
                fv1[nt*2] = c[2]; fv1[nt*2+1] = c[3];
            }
            const float* ab = S_ab + (((bb << 2) + hl) << 6);
            const float SC = 0.17677669529663687f;
            #pragma unroll
            for (int r = 0; r < 2; r++) {
                float* fv = r ? fv1 : fv0;
                int n = mt * 16 + g + (r << 3);
                const unsigned char* bi = S_bi + (n << 6) + (t << 1);
                #pragma unroll
                for (int nt = 0; nt < 8; nt++) {
                    uint16_t b2 = *(const uint16_t*)(bi + (nt << 3));
                    fv[nt*2]   = fv[nt*2]   * SC + ab[b2 & 255u];
                    fv[nt*2+1] = fv[nt*2+1] * SC + ab[b2 >> 8];
                }
                float mx = fv[0];
                #pragma unroll
                for (int j = 1; j < 16; j++) mx = fmaxf(mx, fv[j]);
                mx = fmaxf(mx, __shfl_xor_sync(0xffffffffu, mx, 1));
                mx = fmaxf(mx, __shfl_xor_sync(0xffffffffu, mx, 2));
                float sum = 0.f;
                #pragma unroll
                for (int j = 0; j < 16; j++) { fv[j] = __expf(fv[j] - mx); sum += fv[j]; }
                sum += __shfl_xor_sync(0xffffffffu, sum, 1);
                sum += __shfl_xor_sync(0xffffffffu, sum, 2);
                float inv = 1.f / sum;
                __half* pr = P + hl * PHEAD + n * PSTR + (t << 1);
                #pragma unroll
                for (int nt = 0; nt < 8; nt++)
                    *(__half2*)(pr + (nt << 3)) =
                        __floats2half2_rn(fv[nt*2] * inv, fv[nt*2+1] * inv);
            }
            barn(3, 512);                  // P visible to all PV warps

            // ---- B2(bb): 4 chained heads, PV via HMMA ----
            const int mt2 = wid >> 3;
            const int nt2 = wid & 7;
            for (int hl2 = 0; hl2 < 4; hl2++) {
                const int hd  = (bb << 2) + hl2;
                const int ch0 = hd << 5;
                float c[4] = {0.f, 0.f, 0.f, 0.f};
                const __half* ab2 = V16 + (mt2 * 16 + g) * VSTR + (t << 1);
                const __half* bb2 = P + hl2 * PHEAD + ((nt2 << 3) + g) * PSTR + (t << 1);
                #pragma unroll
                for (int ks = 0; ks < 4; ks++) {
                    uint32_t a4[4], b0, b1;
                    a4[0] = *(const uint32_t*)(ab2 + (ks << 4));
                    a4[1] = *(const uint32_t*)(ab2 + 8 * VSTR + (ks << 4));
                    a4[2] = *(const uint32_t*)(ab2 + (ks << 4) + 8);
                    a4[3] = *(const uint32_t*)(ab2 + 8 * VSTR + (ks << 4) + 8);
                    b0 = *(const uint32_t*)(bb2 + (ks << 4));
                    b1 = *(const uint32_t*)(bb2 + (ks << 4) + 8);
                    hmma16816(c, a4, b0, b1);
                }
                barn(3, 512);              // V16 reads complete
                int d0 = mt2 * 16 + g;
                int n0 = (nt2 << 3) + (t << 1);
                actT[n0 * 264 + ch0 + d0]           = __float2half(fmaxf(c[0], 0.f));
                actT[(n0 + 1) * 264 + ch0 + d0]     = __float2half(fmaxf(c[1], 0.f));
                actT[n0 * 264 + ch0 + d0 + 8]       = __float2half(fmaxf(c[2], 0.f));
                actT[(n0 + 1) * 264 + ch0 + d0 + 8] = __float2half(fmaxf(c[3], 0.f));
                if (hd < 7) {
                    float2 f0 = __half22float2(*(const __half2*)(LL16 + ((ch0 + 32 + d0) << 6) + n0));
                    float2 f1 = __half22float2(*(const __half2*)(LL16 + ((ch0 + 40 + d0) << 6) + n0));
                    *(__half2*)(V16 + d0 * VSTR + n0)       = __floats2half2_rn(c[0] + f0.x, c[1] + f0.y);
                    *(__half2*)(V16 + (d0 + 8) * VSTR + n0) = __floats2half2_rn(c[2] + f1.x, c[3] + f1.y);
                }
                barn(3, 512);              // V16 writes visible
            }
        } else {
            barn(4, 1024);                 // wait for B1b(bb)'s Q reads
            if (bb == 0) {
                // ---- B1a(batch1): q-conv channels 128..255, warps 16-31 ----
                #pragma unroll
                for (int rep = 0; rep < 8; rep++) {
                    int e  = (tid - 512) + rep * 512;   // 4096 strips
                    int cl = e >> 5;                    // warp-uniform
                    int s  = e & 31;
                    int py = s >> 2;
                    int px0 = (s & 3) << 1;
                    int base = px0 >> 1;
                    const float* wd = dww + 3200 + cl * 25;
                    float a0 = __ldg(dwb + 128 + cl), a1 = a0;
                    const __half2* row = (const __half2*)(S_lh + ((128 + cl) << 6));
                    #pragma unroll
                    for (int uu = 0; uu < 5; uu++) {
                        int yy = py + uu - 2;
                        if ((unsigned)yy < 8u) {
                            const __half2* r = row + (yy << 2);
                            const float* w = wd + uu * 5;
                            if (base >= 1) {
                                float2 h = __half22float2(r[base - 1]);
                                a0 += h.x * w[0] + h.y * w[1];
                                a1 += h.y * w[0];
                            }
                            {
                                float2 h = __half22float2(r[base]);
                                a0 += h.x * w[2] + h.y * w[3];
                                a1 += h.x * w[1] + h.y * w[2];
                            }
                            if (base <= 2) {
                                float2 h = __half22float2(r[base + 1]);
                                a0 += h.x * w[4];
                                a1 += h.x * w[3] + h.y * w[4];
                            }
                        }
                    }
                    int n = (py << 3) + px0;
                    Q[n * QS + cl]       = __float2half(a0);
                    Q[(n + 1) * QS + cl] = __float2half(a1);
                }
            } else {
                // ---- prefetch iwtf into dead Q region ----
                #pragma unroll
                for (int rep = 0; rep < 8; rep++)
                    IW[(tid - 512) + rep * 512] = iwtf[(tid - 512) + rep * 512];
            }
        }
        __syncthreads();
    }

    // ===== Phase C: HMMA projection (actT built by B2) =====
    {
        const int mt = wid >> 1;
        const int nh = wid & 1;
        const int g  = lane >> 2;
        const int t  = lane & 3;
        float acc[4][4];
        #pragma unroll
        for (int i = 0; i < 4; i++)
            #pragma unroll
            for (int j = 0; j < 4; j++) acc[i][j] = 0.f;

        const uint4* afrag = (const uint4*)g_WpH + (mt << 9) + lane;
        const __half* bbase = actT + ((nh << 5) + g) * 264 + (t << 1);
        #pragma unroll 4
        for (int ks = 0; ks < 16; ks++) {
            uint4 a = afrag[ks << 5];
            const __half* bp = bbase + (ks << 4);
            #pragma unroll
            for (int ntl = 0; ntl < 4; ntl++) {
                uint32_t b0 = *(const uint32_t*)(bp + ntl * 8 * 264);
                uint32_t b1 = *(const uint32_t*)(bp + ntl * 8 * 264 + 8);
                hmma16816(acc[ntl], (const uint32_t*)&a, b0, b1);
            }
        }
        // epilogue: bias + store to split proj_out (disjoint from actT reads)
        int o0 = (mt << 4) + g;
        float pb0 = pjb[o0], pb1 = pjb[o0 + 8];
        float* d0 = (o0 < 128) ? (PO_LO + (o0 << 6)) : (PO_HI + ((o0 - 128) << 6));
        float* d1 = (o0 < 128) ? (PO_LO + ((o0 + 8) << 6)) : (PO_HI + ((o0 - 120) << 6));
        int ncol = (nh << 5) + (t << 1);
        #pragma unroll
        for (int ntl = 0; ntl < 4; ntl++) {
            int nc = ncol + (ntl << 3);
            *(float2*)(d0 + nc) = make_float2(acc[ntl][0] + pb0, acc[ntl][1] + pb0);
            *(float2*)(d1 + nc) = make_float2(acc[ntl][2] + pb1, acc[ntl][3] + pb1);
        }
    }
    __syncthreads();

    // ================= Phase D: inverse wavelet -> out =================
    {
        float* ob = out + (size_t)wb * (256u * 256u * 256u);
        #pragma unroll 4
        for (int rep = 0; rep < 8; rep++) {
            int u = tid + rep * NTH;
            int c = u >> 5;
            int i = (u >> 2) & 7;
            int k = u & 3;
            int pix = (i << 3) + (k << 1);
            int o0 = (c << 6) + pix;
            const float* w = IW + (c << 4);
            const float* llrow = (c < 128) ? (PO_LO + (c << 6)) : (PO_HI + ((c - 128) << 6));
            float2 llv = *(const float2*)(llrow + pix);
            float2 lh = __half22float2(*(const __half2*)(S_lh + o0));
            float2 hl;
            hl.x = __half2float(hlT[pix * HTS + c]);
            hl.y = __half2float(hlT[(pix + 1) * HTS + c]);
            float2 hh = __half22float2(*(const __half2*)(S_hh + o0));
            float4 r0, r1;
            r0.x = llv.x*w[0] + lh.x*w[4] + hl.x*w[8]  + hh.x*w[12];
            r0.y = llv.x*w[1] + lh.x*w[5] + hl.x*w[9]  + hh.x*w[13];
            r0.z = llv.y*w[0] + lh.y*w[4] + hl.y*w[8]  + hh.y*w[12];
            r0.w = llv.y*w[1] + lh.y*w[5] + hl.y*w[9]  + hh.y*w[13];
            r1.x = llv.x*w[2] + lh.x*w[6] + hl.x*w[10] + hh.x*w[14];
            r1.y = llv.x*w[3] + lh.x*w[7] + hl.x*w[11] + hh.x*w[15];
            r1.z = llv.y*w[2] + lh.y*w[6] + hl.y*w[10] + hh.y*w[14];
            r1.w = llv.y*w[3] + lh.y*w[7] + hl.y*w[11] + hh.y*w[15];
            int gy = (wy << 4) + (i << 1);
            int gx = (wx << 4) + (k << 2);
            float* q_ = ob + (((c << 8) + gy) << 8) + gx;
            *(float4*)q_ = r0;
            *(float4*)(q_ + 256) = r1;
        }
    }
}

extern "C" void kernel_launch(void* const* d_in, const int* in_sizes, int n_in,
                              void* d_out, int out_size) {
    const float* x    = (const float*)d_in[0];
    const float* wtf  = (const float*)d_in[1];
    const float* iwtf = (const float*)d_in[2];
    const float* dww  = (const float*)d_in[3];
    const float* dwb  = (const float*)d_in[4];
    const float* pjw  = (const float*)d_in[5];
    const float* pjb  = (const float*)d_in[6];
    const float* atb  = (const float*)d_in[7];
    const int*   bix  = (const int*)d_in[8];
    float* o = (float*)d_out;
    (void)in_sizes; (void)n_in; (void)out_size;
    prep_kernel<<<256, 256>>>(pjw);
    cudaFuncSetAttribute(wwa_kernel, cudaFuncAttributeMaxDynamicSharedMemorySize, SMEM_BYTES);
    wwa_kernel<<<512, NTH, SMEM_BYTES>>>(x, wtf, iwtf, dww, dwb, pjb, atb, bix, o);
}

// round 13
// speedup vs baseline: 6.3049x; 1.0229x over previous
#include <cuda_runtime.h>
#include <cuda_fp16.h>
#include <cstdint>

// WaveletWindowAttention fused kernel (R12): 1024 threads/CTA, 512 CTAs.
// vs R11: attention bias pre-expanded into HMMA C-fragment order (g_BiasC,
// bias/SCALE) and loaded as accumulator init — softmax gather removed;
// V16 double-buffered with per-group 256-thread barriers (1 per head).

#define NTH 1024
#define PSTR 72           // P row stride in halves
#define PHEAD 4608        // 64*72 halves per head
#define VSTR 72           // V16 row stride in halves
#define QS 134            // Q [n][cl] row stride in halves
#define HTS 258           // hlT [m][c] row stride in halves

__device__ __half g_WpH[65536];   // proj weights fp16 in HMMA A-fragment order
__device__ float  g_BiasC[32768]; // bias/SCALE in HMMA C-fragment order

// prep: pjw[o][c] fp32 -> g_WpH in [mt(16)][ks(16)][lane(32)][aidx(8)] order
__global__ void prep_kernel(const float* __restrict__ pjw) {
    int i = blockIdx.x * 256 + threadIdx.x;   // 65536
    int o = i >> 8, c = i & 255;
    int mt = o >> 4, m = o & 15;
    int ks = c >> 4, k = c & 15;
    int lane = ((m & 7) << 2) | ((k & 7) >> 1);
    int aidx = (k & 1) | (((m >> 3) & 1) << 1) | ((k >> 3) << 2);
    g_WpH[(((((mt << 4) + ks) << 5) + lane) << 3) + aidx] =
        __float2half(pjw[(o << 8) + c]);
}

// prep: bias matrix -> g_BiasC[h][mt][nt][lane] float4 (bias / SCALE)
__global__ void prep_bias(const float* __restrict__ atb,
                          const int* __restrict__ bix) {
    int tid = blockIdx.x * 256 + threadIdx.x;   // 8192
    int h = tid >> 10, mt = (tid >> 8) & 3, nt = (tid >> 5) & 7, lane = tid & 31;
    int g = lane >> 2, t = lane & 3;
    int n0 = mt * 16 + g, m0 = nt * 8 + t * 2;
    const float INV = 5.656854249492381f;       // 1/SCALE
    float4 v;
    v.x = atb[(h << 6) + bix[(n0 << 6) + m0]]       * INV;
    v.y = atb[(h << 6) + bix[(n0 << 6) + m0 + 1]]   * INV;
    v.z = atb[(h << 6) + bix[((n0 + 8) << 6) + m0]] * INV;
    v.w = atb[(h << 6) + bix[((n0 + 8) << 6) + m0 + 1]] * INV;
    ((float4*)g_BiasC)[tid] = v;
}

__device__ __forceinline__ void hmma16816(float* c4, const uint32_t* a4,
                                          uint32_t b0, uint32_t b1) {
    asm volatile(
        "mma.sync.aligned.m16n8k16.row.col.f32.f16.f16.f32 "
        "{%0,%1,%2,%3}, {%4,%5,%6,%7}, {%8,%9}, {%0,%1,%2,%3};"
        : "+f"(c4[0]), "+f"(c4[1]), "+f"(c4[2]), "+f"(c4[3])
        : "r"(a4[0]), "r"(a4[1]), "r"(a4[2]), "r"(a4[3]), "r"(b0), "r"(b1));
}

__device__ __forceinline__ void barn(int id, int cnt) {
    asm volatile("bar.sync %0, %1;" :: "r"(id), "r"(cnt) : "memory");
}

// ---- shared memory layout (bytes) ----
// @0      LL16 f16 [256][64] (32768) | PO_LO f32 [128][64] (phase C/D)
// @32768  S_lh f16 [256][64] (32768)
// @65536  hlT  f16 [64][258] (33024)
// @98560  S_hh f16 [256][64] (32768)
// @131328 P f16 [4][64][72] (36864) | S_wt(A) | PO_HI f32 [128][64]
// @168192 Q f16 [64][134]   (17152) | IW f32[4096] (loaded during B2(b1))
// @185344 actT f16 [64][264] (33792)
// @219136 V16A f16 [32][72] (4608)
// @223744 V16B f16 [32][72] (4608)  -> end 228352
#define SMEM_BYTES 228352

__global__ void __launch_bounds__(NTH, 1)
wwa_kernel(const float* __restrict__ x,   const float* __restrict__ wtf,
           const float* __restrict__ iwtf,const float* __restrict__ dww,
           const float* __restrict__ dwb, const float* __restrict__ pjb,
           float* __restrict__ out)
{
    extern __shared__ unsigned char sm[];
    __half* LL16 = (__half*)sm;
    __half* S_lh = (__half*)(sm + 32768);
    __half* hlT  = (__half*)(sm + 65536);
    __half* S_hh = (__half*)(sm + 98560);
    __half* P    = (__half*)(sm + 131328);
    float*  S_wt = (float*)(sm + 131328);
    float*  PO_LO = (float*)sm;                 // proj rows 0..127
    float*  PO_HI = (float*)(sm + 131328);      // proj rows 128..255
    __half* Q    = (__half*)(sm + 168192);
    float*  IW   = (float*)(sm + 168192);       // iwtf, loaded during B2(b1)
    __half* actT = (__half*)(sm + 185344);
    __half* V16A = (__half*)(sm + 219136);
    __half* V16B = (__half*)(sm + 223744);

    const int tid  = threadIdx.x;
    const int wid  = tid >> 5;
    const int lane = tid & 31;
    const int widx = blockIdx.x;
    const int wb = widx >> 8;
    const int wy = (widx >> 4) & 15;
    const int wx = widx & 15;

    // ---- init: wavelet filters ----
    for (int i = tid; i < 4096; i += NTH) S_wt[i] = wtf[i];
    __syncthreads();

    // ================= Phase A: forward wavelet =================
    {
        const float* xb = x + (size_t)wb * (256u * 256u * 256u);
        #pragma unroll 4
        for (int rep = 0; rep < 8; rep++) {
            int u = tid + rep * NTH;        // (c, i, k)
            int c = u >> 5;
            int i = (u >> 2) & 7;
            int k = u & 3;
            int gy = (wy << 4) + (i << 1);
            int gx = (wx << 4) + (k << 2);
            const float* p = xb + (((c << 8) + gy) << 8) + gx;
            float4 a = *(const float4*)p;
            float4 b = *(const float4*)(p + 256);
            const float* w = S_wt + (c << 4);
            int pix = (i << 3) + (k << 1);
            int o0 = (c << 6) + pix;
            float v0, v1;
            v0 = a.x*w[0] + a.y*w[1] + b.x*w[2] + b.y*w[3];
            v1 = a.z*w[0] + a.w*w[1] + b.z*w[2] + b.w*w[3];
            *(__half2*)(LL16 + o0) = __floats2half2_rn(v0, v1);
            v0 = a.x*w[4] + a.y*w[5] + b.x*w[6] + b.y*w[7];
            v1 = a.z*w[4] + a.w*w[5] + b.z*w[6] + b.w*w[7];
            *(__half2*)(S_lh + o0) = __floats2half2_rn(v0, v1);
            v0 = a.x*w[8] + a.y*w[9] + b.x*w[10] + b.y*w[11];
            v1 = a.z*w[8] + a.w*w[9] + b.z*w[10] + b.w*w[11];
            hlT[pix * HTS + c]       = __float2half(v0);
            hlT[(pix + 1) * HTS + c] = __float2half(v1);
            v0 = a.x*w[12] + a.y*w[13] + b.x*w[14] + b.y*w[15];
            v1 = a.z*w[12] + a.w*w[13] + b.z*w[14] + b.w*w[15];
            *(__half2*)(S_hh + o0) = __floats2half2_rn(v0, v1);
        }
    }
    __syncthreads();

    // head-0 v init: V16A[d][m] = LL16[d][m]
    {
        int d  = tid >> 5;
        int m2 = (tid & 31) << 1;
        *(__half2*)(V16A + d * VSTR + m2) = *(const __half2*)(LL16 + (d << 6) + m2);
    }

    // ---- B1a(batch0): q-conv channels 0..127, all 32 warps ----
    #pragma unroll
    for (int rep = 0; rep < 4; rep++) {
        int e  = tid + rep * NTH;      // 4096 strips
        int cl = e >> 5;               // warp-uniform
        int s  = e & 31;
        int py = s >> 2;
        int px0 = (s & 3) << 1;
        int base = px0 >> 1;
        const float* wd = dww + cl * 25;
        float a0 = __ldg(dwb + cl), a1 = a0;
        const __half2* row = (const __half2*)(S_lh + (cl << 6));
        #pragma unroll
        for (int uu = 0; uu < 5; uu++) {
            int yy = py + uu - 2;
            if ((unsigned)yy < 8u) {
                const __half2* r = row + (yy << 2);
                const float* w = wd + uu * 5;
                if (base >= 1) {
                    float2 h = __half22float2(r[base - 1]);
                    a0 += h.x * w[0] + h.y * w[1];
                    a1 += h.y * w[0];
                }
                {
                    float2 h = __half22float2(r[base]);
                    a0 += h.x * w[2] + h.y * w[3];
                    a1 += h.x * w[1] + h.y * w[2];
                }
                if (base <= 2) {
                    float2 h = __half22float2(r[base + 1]);
                    a0 += h.x * w[4];
                    a1 += h.x * w[3] + h.y * w[4];
                }
            }
        }
        int n = (py << 3) + px0;
        Q[n * QS + cl]       = __float2half(a0);
        Q[(n + 1) * QS + cl] = __float2half(a1);
    }
    __syncthreads();

    // ================= Phase B: 2 batches, warp-specialized =================
    for (int bb = 0; bb < 2; bb++) {
        if (wid < 16) {
            // ---- B1b(bb): QK^T via HMMA, bias as C-init, reg softmax -> P ----
            const int hl = wid >> 2;
            const int mt = wid & 3;
            const int g  = lane >> 2;
            const int t  = lane & 3;
            const int chb = hl << 5;
            // bias C-init (L2-resident, fragment order)
            float fv0[16], fv1[16];
            {
                const float4* bc = (const float4*)g_BiasC
                    + ((((bb << 2) + hl) * 4 + mt) << 8) + lane;
                #pragma unroll
                for (int nt = 0; nt < 8; nt++) {
                    float4 b4 = bc[nt << 5];
                    fv0[nt*2] = b4.x; fv0[nt*2+1] = b4.y;
                    fv1[nt*2] = b4.z; fv1[nt*2+1] = b4.w;
                }
            }
            const __half* qb = Q + (mt * 16 + g) * QS + chb + (t << 1);
            uint32_t A0[4], A1[4];
            A0[0] = *(const uint32_t*)(qb);
            A0[1] = *(const uint32_t*)(qb + 8 * QS);
            A0[2] = *(const uint32_t*)(qb + 8);
            A0[3] = *(const uint32_t*)(qb + 8 * QS + 8);
            A1[0] = *(const uint32_t*)(qb + 16);
            A1[1] = *(const uint32_t*)(qb + 8 * QS + 16);
            A1[2] = *(const uint32_t*)(qb + 24);
            A1[3] = *(const uint32_t*)(qb + 8 * QS + 24);
            barn(4, 1024);                 // Q reads done -> other half may reuse Q
            const __half* bt = hlT + (bb << 7) + chb + (t << 1);
            #pragma unroll
            for (int nt = 0; nt < 8; nt++) {
                float c[4] = {fv0[nt*2], fv0[nt*2+1], fv1[nt*2], fv1[nt*2+1]};
                const __half* bp = bt + ((nt << 3) + g) * HTS;
                uint32_t b0 = *(const uint32_t*)(bp);
                uint32_t b1 = *(const uint32_t*)(bp + 8);
                hmma16816(c, A0, b0, b1);
                b0 = *(const uint32_t*)(bp + 16);
                b1 = *(const uint32_t*)(bp + 24);
                hmma16816(c, A1, b0, b1);
                fv0[nt*2] = c[0]; fv0[nt*2+1] = c[1];
                fv1[nt*2] = c[2]; fv1[nt*2+1] = c[3];
            }
            const float SC = 0.17677669529663687f;
            #pragma unroll
            for (int r = 0; r < 2; r++) {
                float* fv = r ? fv1 : fv0;
                int n = mt * 16 + g + (r << 3);
                #pragma unroll
                for (int j = 0; j < 16; j++) fv[j] *= SC;
                float mx = fv[0];
                #pragma unroll
                for (int j = 1; j < 16; j++) mx = fmaxf(mx, fv[j]);
                mx = fmaxf(mx, __shfl_xor_sync(0xffffffffu, mx, 1));
                mx = fmaxf(mx, __shfl_xor_sync(0xffffffffu, mx, 2));
                float sum = 0.f;
                #pragma unroll
                for (int j = 0; j < 16; j++) { fv[j] = __expf(fv[j] - mx); sum += fv[j]; }
                sum += __shfl_xor_sync(0xffffffffu, sum, 1);
                sum += __shfl_xor_sync(0xffffffffu, sum, 2);
                float inv = 1.f / sum;
                __half* pr = P + hl * PHEAD + n * PSTR + (t << 1);
                #pragma unroll
                for (int nt = 0; nt < 8; nt++)
                    *(__half2*)(pr + (nt << 3)) =
                        __floats2half2_rn(fv[nt*2] * inv, fv[nt*2+1] * inv);
            }
            barn(3, 512);                  // P visible to all PV warps

            // ---- B2(bb): 4 chained heads, PV via HMMA, V16 double-buffered ----
            const int mt2 = wid >> 3;
            const int nt2 = wid & 7;
            for (int hl2 = 0; hl2 < 4; hl2++) {
                const int hd  = (bb << 2) + hl2;
                const int ch0 = hd << 5;
                __half* Vcur = (hd & 1) ? V16B : V16A;
                __half* Vnxt = (hd & 1) ? V16A : V16B;
                float c[4] = {0.f, 0.f, 0.f, 0.f};
                const __half* ab2 = Vcur + (mt2 * 16 + g) * VSTR + (t << 1);
                const __half* bb2 = P + hl2 * PHEAD + ((nt2 << 3) + g) * PSTR + (t << 1);
                #pragma unroll
                for (int ks = 0; ks < 4; ks++) {
                    uint32_t a4[4], b0, b1;
                    a4[0] = *(const uint32_t*)(ab2 + (ks << 4));
                    a4[1] = *(const uint32_t*)(ab2 + 8 * VSTR + (ks << 4));
                    a4[2] = *(const uint32_t*)(ab2 + (ks << 4) + 8);
                    a4[3] = *(const uint32_t*)(ab2 + 8 * VSTR + (ks << 4) + 8);
                    b0 = *(const uint32_t*)(bb2 + (ks << 4));
                    b1 = *(const uint32_t*)(bb2 + (ks << 4) + 8);
                    hmma16816(c, a4, b0, b1);
                }
                int d0 = mt2 * 16 + g;
                int n0 = (nt2 << 3) + (t << 1);
                actT[n0 * 264 + ch0 + d0]           = __float2half(fmaxf(c[0], 0.f));
                actT[(n0 + 1) * 264 + ch0 + d0]     = __float2half(fmaxf(c[1], 0.f));
                actT[n0 * 264 + ch0 + d0 + 8]       = __float2half(fmaxf(c[2], 0.f));
                actT[(n0 + 1) * 264 + ch0 + d0 + 8] = __float2half(fmaxf(c[3], 0.f));
                if (hd < 7) {
                    float2 f0 = __half22float2(*(const __half2*)(LL16 + ((ch0 + 32 + d0) << 6) + n0));
                    float2 f1 = __half22float2(*(const __half2*)(LL16 + ((ch0 + 40 + d0) << 6) + n0));
                    *(__half2*)(Vnxt + d0 * VSTR + n0)       = __floats2half2_rn(c[0] + f0.x, c[1] + f0.y);
                    *(__half2*)(Vnxt + (d0 + 8) * VSTR + n0) = __floats2half2_rn(c[2] + f1.x, c[3] + f1.y);
                }
                barn(5 + mt2, 256);        // Vnxt writes visible within group
            }
        } else {
            barn(4, 1024);                 // wait for B1b(bb)'s Q reads
            if (bb == 0) {
                // ---- B1a(batch1): q-conv channels 128..255, warps 16-31 ----
                #pragma unroll
                for (int rep = 0; rep < 8; rep++) {
                    int e  = (tid - 512) + rep * 512;   // 4096 strips
                    int cl = e >> 5;                    // warp-uniform
                    int s  = e & 31;
                    int py = s >> 2;
                    int px0 = (s & 3) << 1;
                    int base = px0 >> 1;
                    const float* wd = dww + 3200 + cl * 25;
                    float a0 = __ldg(dwb + 128 + cl), a1 = a0;
                    const __half2* row = (const __half2*)(S_lh + ((128 + cl) << 6));
                    #pragma unroll
                    for (int uu = 0; uu < 5; uu++) {
                        int yy = py + uu - 2;
                        if ((unsigned)yy < 8u) {
                            const __half2* r = row + (yy << 2);
                            const float* w = wd + uu * 5;
                            if (base >= 1) {
                                float2 h = __half22float2(r[base - 1]);
                                a0 += h.x * w[0] + h.y * w[1];
                                a1 += h.y * w[0];
                            }
                            {
                                float2 h = __half22float2(r[base]);
                                a0 += h.x * w[2] + h.y * w[3];
                                a1 += h.x * w[1] + h.y * w[2];
                            }
                            if (base <= 2) {
                                float2 h = __half22float2(r[base + 1]);
                                a0 += h.x * w[4];
                                a1 += h.x * w[3] + h.y * w[4];
                            }
                        }
                    }
                    int n = (py << 3) + px0;
                    Q[n * QS + cl]       = __float2half(a0);
                    Q[(n + 1) * QS + cl] = __float2half(a1);
                }
            } else {
                // ---- prefetch iwtf into dead Q region ----
                #pragma unroll
                for (int rep = 0; rep < 8; rep++)
                    IW[(tid - 512) + rep * 512] = iwtf[(tid - 512) + rep * 512];
            }
        }
        __syncthreads();
    }

    // ===== Phase C: HMMA projection (actT built by B2) =====
    {
        const int mt = wid >> 1;
        const int nh = wid & 1;
        const int g  = lane >> 2;
        const int t  = lane & 3;
        float acc[4][4];
        #pragma unroll
        for (int i = 0; i < 4; i++)
            #pragma unroll
            for (int j = 0; j < 4; j++) acc[i][j] = 0.f;

        const uint4* afrag = (const uint4*)g_WpH + (mt << 9) + lane;
        const __half* bbase = actT + ((nh << 5) + g) * 264 + (t << 1);
        #pragma unroll 4
        for (int ks = 0; ks < 16; ks++) {
            uint4 a = afrag[ks << 5];
            const __half* bp = bbase + (ks << 4);
            #pragma unroll
            for (int ntl = 0; ntl < 4; ntl++) {
                uint32_t b0 = *(const uint32_t*)(bp + ntl * 8 * 264);
                uint32_t b1 = *(const uint32_t*)(bp + ntl * 8 * 264 + 8);
                hmma16816(acc[ntl], (const uint32_t*)&a, b0, b1);
            }
        }
        // epilogue: bias + store to split proj_out (disjoint from actT reads)
        int o0 = (mt << 4) + g;
        float pb0 = pjb[o0], pb1 = pjb[o0 + 8];
        float* d0 = (o0 < 128) ? (PO_LO + (o0 << 6)) : (PO_HI + ((o0 - 128) << 6));
        float* d1 = (o0 < 128) ? (PO_LO + ((o0 + 8) << 6)) : (PO_HI + ((o0 - 120) << 6));
        int ncol = (nh << 5) + (t << 1);
        #pragma unroll
        for (int ntl = 0; ntl < 4; ntl++) {
            int nc = ncol + (ntl << 3);
            *(float2*)(d0 + nc) = make_float2(acc[ntl][0] + pb0, acc[ntl][1] + pb0);
            *(float2*)(d1 + nc) = make_float2(acc[ntl][2] + pb1, acc[ntl][3] + pb1);
        }
    }
    __syncthreads();

    // ================= Phase D: inverse wavelet -> out =================
    {
        float* ob = out + (size_t)wb * (256u * 256u * 256u);
        #pragma unroll 4
        for (int rep = 0; rep < 8; rep++) {
            int u = tid + rep * NTH;
            int c = u >> 5;
            int i = (u >> 2) & 7;
            int k = u & 3;
            int pix = (i << 3) + (k << 1);
            int o0 = (c << 6) + pix;
            const float* w = IW + (c << 4);
            const float* llrow = (c < 128) ? (PO_LO + (c << 6)) : (PO_HI + ((c - 128) << 6));
            float2 llv = *(const float2*)(llrow + pix);
            float2 lh = __half22float2(*(const __half2*)(S_lh + o0));
            float2 hl;
            hl.x = __half2float(hlT[pix * HTS + c]);
            hl.y = __half2float(hlT[(pix + 1) * HTS + c]);
            float2 hh = __half22float2(*(const __half2*)(S_hh + o0));
            float4 r0, r1;
            r0.x = llv.x*w[0] + lh.x*w[4] + hl.x*w[8]  + hh.x*w[12];
            r0.y = llv.x*w[1] + lh.x*w[5] + hl.x*w[9]  + hh.x*w[13];
            r0.z = llv.y*w[0] + lh.y*w[4] + hl.y*w[8]  + hh.y*w[12];
            r0.w = llv.y*w[1] + lh.y*w[5] + hl.y*w[9]  + hh.y*w[13];
            r1.x = llv.x*w[2] + lh.x*w[6] + hl.x*w[10] + hh.x*w[14];
            r1.y = llv.x*w[3] + lh.x*w[7] + hl.x*w[11] + hh.x*w[15];
            r1.z = llv.y*w[2] + lh.y*w[6] + hl.y*w[10] + hh.y*w[14];
            r1.w = llv.y*w[3] + lh.y*w[7] + hl.y*w[11] + hh.y*w[15];
            int gy = (wy << 4) + (i << 1);
            int gx = (wx << 4) + (k << 2);
            float* q_ = ob + (((c << 8) + gy) << 8) + gx;
            *(float4*)q_ = r0;
            *(float4*)(q_ + 256) = r1;
        }
    }
}

extern "C" void kernel_launch(void* const* d_in, const int* in_sizes, int n_in,
                              void* d_out, int out_size) {
    const float* x    = (const float*)d_in[0];
    const float* wtf  = (const float*)d_in[1];
    const float* iwtf = (const float*)d_in[2];
    const float* dww  = (const float*)d_in[3];
    const float* dwb  = (const float*)d_in[4];
    const float* pjw  = (const float*)d_in[5];
    const float* pjb  = (const float*)d_in[6];
    const float* atb  = (const float*)d_in[7];
    const int*   bix  = (const int*)d_in[8];
    float* o = (float*)d_out;
    (void)in_sizes; (void)n_in; (void)out_size;
    prep_kernel<<<256, 256>>>(pjw);
    prep_bias<<<32, 256>>>(atb, bix);
    cudaFuncSetAttribute(wwa_kernel, cudaFuncAttributeMaxDynamicSharedMemorySize, SMEM_BYTES);
    wwa_kernel<<<512, NTH, SMEM_BYTES>>>(x, wtf, iwtf, dww, dwb, pjb, o);
}